// round 11
// baseline (speedup 1.0000x reference)
#include <cuda_runtime.h>
#include <math.h>

#define NN 10000
#define NE 160000
#define MM 9
#define CC 64
#define HH 8

// ---------------- scratch (static device globals; no allocation) ----------------
__device__ float    g_xs[NN*MM*CC];        // node src-linear   (23 MB)
__device__ float    g_xd[NN*MM*CC];        // node dst-linear   (23 MB)
__device__ float    g_wlc[(size_t)NE*192]; // radial weights    (123 MB)
__device__ float    g_m0[(size_t)NE*64];   // msg row 0         (41 MB)
__device__ float    g_gate[(size_t)NE*64]; // sigmoid(gate)     (41 MB)
__device__ float    g_logit[NE*HH];
__device__ unsigned g_nmax[NN*HH];         // monotone-mapped float max
__device__ float    g_denom[NN*HH];
__device__ float    g_acc[NN*MM*CC];

__device__ __forceinline__ unsigned fkey(float f){
    int i = __float_as_int(f);
    return (i >= 0) ? ((unsigned)i ^ 0x80000000u) : ~(unsigned)i;
}
__device__ __forceinline__ float fdec(unsigned u){
    int i = (u & 0x80000000u) ? (int)(u ^ 0x80000000u) : (int)(~u);
    return __int_as_float(i);
}
__device__ __forceinline__ float sigf(float x){ return 1.f/(1.f + __expf(-x)); }

// packed fp32x2 FMA: d = a*b + d
__device__ __forceinline__ void ffma2(unsigned long long& d,
                                      unsigned long long a,
                                      unsigned long long b){
    asm("fma.rn.f32x2 %0, %1, %2, %0;" : "+l"(d) : "l"(a), "l"(b));
}
__device__ __forceinline__ float2 up2(unsigned long long v){
    float2 r; asm("mov.b64 {%0,%1}, %2;" : "=f"(r.x), "=f"(r.y) : "l"(v)); return r;
}
// pair-scoped named barrier (64 threads)
__device__ __forceinline__ void pbar(int id){
    asm volatile("bar.sync %0, 64;" :: "r"(id) : "memory");
}

__global__ void k_init(){
    int i = blockIdx.x*blockDim.x + threadIdx.x;
    int st = gridDim.x*blockDim.x;
    for (int t = i; t < NN*MM*CC; t += st) g_acc[t] = 0.f;
    for (int t = i; t < NN*HH;    t += st){ g_denom[t] = 0.f; g_nmax[t] = fkey(-INFINITY); }
}

// ================= K1: node linear (GEMM: 4 nodes -> X[40x64] @ W[64x128]) =====
__global__ __launch_bounds__(256) void k_node(
    const float* __restrict__ xin, const float* __restrict__ Ws,
    const float* __restrict__ bs,  const float* __restrict__ Wd)
{
    extern __shared__ float sm[];
    float* s_W = sm;               // [64][128]
    float* s_X = s_W + 64*128;     // [40][68]
    float* s_b = s_X + 40*68;      // 64
    int tid = threadIdx.x;
    for (int t = tid; t < 8192; t += 256){
        int k = t>>7, c = t&127;
        s_W[t] = (c < 64) ? Ws[k*64 + c] : Wd[k*64 + (c-64)];
    }
    if (tid < 64) s_b[tid] = bs[tid];
    for (int t = tid; t < 4*68; t += 256) s_X[36*68 + t] = 0.f;
    __syncthreads();

    int rg = tid>>5;
    int c0 = (tid&31)*4;
    int r0 = rg*5;

    for (int base = blockIdx.x*4; base < NN; base += gridDim.x*4){
        __syncthreads();
        for (int i = tid; i < 4*576; i += 256){
            int n = i/576, rem = i - n*576;
            int row = n*9 + (rem>>6), col = rem&63;
            s_X[row*68 + col] = xin[(size_t)(base+n)*576 + rem];
        }
        __syncthreads();
        float4 a0 = {0,0,0,0}, a1 = a0, a2 = a0, a3 = a0, a4 = a0;
        const float* Xp = s_X + r0*68;
        #pragma unroll 4
        for (int k = 0; k < 64; k += 4){
            float4 w0 = *(const float4*)(s_W + (k  )*128 + c0);
            float4 w1 = *(const float4*)(s_W + (k+1)*128 + c0);
            float4 w2 = *(const float4*)(s_W + (k+2)*128 + c0);
            float4 w3 = *(const float4*)(s_W + (k+3)*128 + c0);
            float4 x0 = *(const float4*)(Xp + k);
            float4 x1 = *(const float4*)(Xp + 68 + k);
            float4 x2 = *(const float4*)(Xp + 136 + k);
            float4 x3 = *(const float4*)(Xp + 204 + k);
            float4 x4 = *(const float4*)(Xp + 272 + k);
            a0.x += x0.x*w0.x + x0.y*w1.x + x0.z*w2.x + x0.w*w3.x;
            a0.y += x0.x*w0.y + x0.y*w1.y + x0.z*w2.y + x0.w*w3.y;
            a0.z += x0.x*w0.z + x0.y*w1.z + x0.z*w2.z + x0.w*w3.z;
            a0.w += x0.x*w0.w + x0.y*w1.w + x0.z*w2.w + x0.w*w3.w;
            a1.x += x1.x*w0.x + x1.y*w1.x + x1.z*w2.x + x1.w*w3.x;
            a1.y += x1.x*w0.y + x1.y*w1.y + x1.z*w2.y + x1.w*w3.y;
            a1.z += x1.x*w0.z + x1.y*w1.z + x1.z*w2.z + x1.w*w3.z;
            a1.w += x1.x*w0.w + x1.y*w1.w + x1.z*w2.w + x1.w*w3.w;
            a2.x += x2.x*w0.x + x2.y*w1.x + x2.z*w2.x + x2.w*w3.x;
            a2.y += x2.x*w0.y + x2.y*w1.y + x2.z*w2.y + x2.w*w3.y;
            a2.z += x2.x*w0.z + x2.y*w1.z + x2.z*w2.z + x2.w*w3.z;
            a2.w += x2.x*w0.w + x2.y*w1.w + x2.z*w2.w + x2.w*w3.w;
            a3.x += x3.x*w0.x + x3.y*w1.x + x3.z*w2.x + x3.w*w3.x;
            a3.y += x3.x*w0.y + x3.y*w1.y + x3.z*w2.y + x3.w*w3.y;
            a3.z += x3.x*w0.z + x3.y*w1.z + x3.z*w2.z + x3.w*w3.z;
            a3.w += x3.x*w0.w + x3.y*w1.w + x3.z*w2.w + x3.w*w3.w;
            a4.x += x4.x*w0.x + x4.y*w1.x + x4.z*w2.x + x4.w*w3.x;
            a4.y += x4.x*w0.y + x4.y*w1.y + x4.z*w2.y + x4.w*w3.y;
            a4.z += x4.x*w0.z + x4.y*w1.z + x4.z*w2.z + x4.w*w3.z;
            a4.w += x4.x*w0.w + x4.y*w1.w + x4.z*w2.w + x4.w*w3.w;
        }
        float4 acc[5] = {a0,a1,a2,a3,a4};
        #pragma unroll
        for (int i = 0; i < 5; i++){
            int r = r0 + i;
            if (r < 36){
                int n = base + r/9, m = r%9;
                float4 v = acc[i];
                if (m == 0 && c0 < 64){
                    v.x += s_b[c0]; v.y += s_b[c0+1]; v.z += s_b[c0+2]; v.w += s_b[c0+3];
                }
                if (c0 < 64) *(float4*)(g_xs + (size_t)n*576 + m*64 + c0) = v;
                else         *(float4*)(g_xd + (size_t)n*576 + m*64 + (c0-64)) = v;
            }
        }
    }
}

// ===== K2: radial MLP + alpha logits, FFMA2 (16 edges/iter, 256t) ===============
__global__ __launch_bounds__(256) void k_edgeA(
    const float* __restrict__ esc, const float* __restrict__ eattr,
    const int* __restrict__ esrc,  const int* __restrict__ edst,
    const float* __restrict__ W1,  const float* __restrict__ b1,
    const float* __restrict__ lng, const float* __restrict__ lnb,
    const float* __restrict__ W2,  const float* __restrict__ off,
    const float* __restrict__ Wa,  const float* __restrict__ ba,
    const float* __restrict__ adot)
{
    extern __shared__ float sm[];
    float* s_W1T = sm;                // [64 slots][68]
    float* s_WaT = s_W1T + 64*68;     // [64 slots][68]
    float* s_W2T = s_WaT + 64*68;     // [192 cols][68]
    float* cb    = s_W2T + 192*68;    // b1|lng|lnb|ba|adot|off = 512
    float* s_S   = cb + 512;          // [16][68]
    float* s_H   = s_S + 16*68;       // [16][68]
    float* s_M0  = s_H + 16*68;       // [16][68]
    float* s_wl0 = s_M0 + 16*68;      // [16][68]
    int tid = threadIdx.x;
    for (int t = tid; t < 4096; t += 256){
        int k = t>>6, j = t&63;
        int slot = (j&3)*16 + (j>>2);
        s_W1T[slot*68 + k] = W1[t];
        s_WaT[slot*68 + k] = Wa[t];
    }
    for (int t = tid; t < 12288; t += 256){
        int k = t/192, c = t - k*192;
        s_W2T[c*68 + k] = W2[t];
    }
    if (tid < 64){
        cb[tid] = b1[tid]; cb[64+tid] = lng[tid]; cb[128+tid] = lnb[tid];
        cb[192+tid] = ba[tid]; cb[256+tid] = adot[tid];
    }
    for (int t = tid; t < 192; t += 256) cb[320+t] = off[t];
    __syncthreads();

    int rg = tid>>4;            // 0..15 (edge row)
    int tx = tid&15;
    int c0 = tx*4;
    const float* W1p0 = s_W1T + tx*68;
    const float* W1p1 = s_W1T + (tx+16)*68;
    const float* W1p2 = s_W1T + (tx+32)*68;
    const float* W1p3 = s_W1T + (tx+48)*68;
    const float* Wap0 = s_WaT + tx*68;
    const float* Wap1 = s_WaT + (tx+16)*68;
    const float* Wap2 = s_WaT + (tx+32)*68;
    const float* Wap3 = s_WaT + (tx+48)*68;

    for (int base = blockIdx.x*16; base < NE; base += gridDim.x*16){
        __syncthreads();
        for (int i = tid; i < 16*64; i += 256){
            int e = i>>6, c = i&63;
            s_S[e*68 + c] = esc[(size_t)(base+e)*64 + c];
        }
        __syncthreads();
        // GEMM1: H = S @ W1  (FFMA2)
        {
            unsigned long long q0=0ull,q1=0ull,q2=0ull,q3=0ull;
            const float* Xp = s_S + rg*68;
            #pragma unroll 4
            for (int k = 0; k < 64; k += 4){
                ulonglong2 x  = *(const ulonglong2*)(Xp + k);
                ulonglong2 w0 = *(const ulonglong2*)(W1p0 + k);
                ulonglong2 w1 = *(const ulonglong2*)(W1p1 + k);
                ulonglong2 w2 = *(const ulonglong2*)(W1p2 + k);
                ulonglong2 w3 = *(const ulonglong2*)(W1p3 + k);
                ffma2(q0, x.x, w0.x); ffma2(q0, x.y, w0.y);
                ffma2(q1, x.x, w1.x); ffma2(q1, x.y, w1.y);
                ffma2(q2, x.x, w2.x); ffma2(q2, x.y, w2.y);
                ffma2(q3, x.x, w3.x); ffma2(q3, x.y, w3.y);
            }
            float2 p0=up2(q0), p1=up2(q1), p2=up2(q2), p3=up2(q3);
            float4 a;
            a.x = p0.x+p0.y + cb[c0  ];
            a.y = p1.x+p1.y + cb[c0+1];
            a.z = p2.x+p2.y + cb[c0+2];
            a.w = p3.x+p3.y + cb[c0+3];
            float s = a.x+a.y+a.z+a.w;
            float q = a.x*a.x+a.y*a.y+a.z*a.z+a.w*a.w;
            #pragma unroll
            for (int o = 8; o > 0; o >>= 1){
                s += __shfl_xor_sync(0xffffffffu, s, o);
                q += __shfl_xor_sync(0xffffffffu, q, o);
            }
            float mu = s*(1.f/64.f);
            float var = q*(1.f/64.f) - mu*mu;
            float rs = rsqrtf(var + 1e-5f);
            float4 h;
            h.x = (a.x-mu)*rs*cb[64+c0  ] + cb[128+c0  ];
            h.y = (a.y-mu)*rs*cb[64+c0+1] + cb[128+c0+1];
            h.z = (a.z-mu)*rs*cb[64+c0+2] + cb[128+c0+2];
            h.w = (a.w-mu)*rs*cb[64+c0+3] + cb[128+c0+3];
            h.x *= sigf(h.x); h.y *= sigf(h.y); h.z *= sigf(h.z); h.w *= sigf(h.w);
            *(float4*)(s_H + rg*68 + c0) = h;
        }
        __syncthreads();
        // GEMM2: WL = H @ W2  (FFMA2, write g_wlc directly, stash wl0)
        {
            int rgr = tid>>6;
            int cc  = tid&63;
            unsigned long long acc[4][3];
            #pragma unroll
            for (int i = 0; i < 4; i++){ acc[i][0]=0ull; acc[i][1]=0ull; acc[i][2]=0ull; }
            const float* Wp0 = s_W2T + cc*68;
            const float* Wp1 = s_W2T + (cc+64)*68;
            const float* Wp2 = s_W2T + (cc+128)*68;
            #pragma unroll 4
            for (int k = 0; k < 64; k += 4){
                ulonglong2 w0 = *(const ulonglong2*)(Wp0 + k);
                ulonglong2 w1 = *(const ulonglong2*)(Wp1 + k);
                ulonglong2 w2 = *(const ulonglong2*)(Wp2 + k);
                ulonglong2 x0 = *(const ulonglong2*)(s_H + (rgr   )*68 + k);
                ulonglong2 x1 = *(const ulonglong2*)(s_H + (rgr+4 )*68 + k);
                ulonglong2 x2 = *(const ulonglong2*)(s_H + (rgr+8 )*68 + k);
                ulonglong2 x3 = *(const ulonglong2*)(s_H + (rgr+12)*68 + k);
                ffma2(acc[0][0], x0.x, w0.x); ffma2(acc[0][0], x0.y, w0.y);
                ffma2(acc[0][1], x0.x, w1.x); ffma2(acc[0][1], x0.y, w1.y);
                ffma2(acc[0][2], x0.x, w2.x); ffma2(acc[0][2], x0.y, w2.y);
                ffma2(acc[1][0], x1.x, w0.x); ffma2(acc[1][0], x1.y, w0.y);
                ffma2(acc[1][1], x1.x, w1.x); ffma2(acc[1][1], x1.y, w1.y);
                ffma2(acc[1][2], x1.x, w2.x); ffma2(acc[1][2], x1.y, w2.y);
                ffma2(acc[2][0], x2.x, w0.x); ffma2(acc[2][0], x2.y, w0.y);
                ffma2(acc[2][1], x2.x, w1.x); ffma2(acc[2][1], x2.y, w1.y);
                ffma2(acc[2][2], x2.x, w2.x); ffma2(acc[2][2], x2.y, w2.y);
                ffma2(acc[3][0], x3.x, w0.x); ffma2(acc[3][0], x3.y, w0.y);
                ffma2(acc[3][1], x3.x, w1.x); ffma2(acc[3][1], x3.y, w1.y);
                ffma2(acc[3][2], x3.x, w2.x); ffma2(acc[3][2], x3.y, w2.y);
            }
            #pragma unroll
            for (int i = 0; i < 4; i++){
                int r = rgr + i*4;
                #pragma unroll
                for (int j = 0; j < 3; j++){
                    float2 p = up2(acc[i][j]);
                    float v = p.x + p.y + cb[320 + cc + 64*j];
                    g_wlc[(size_t)(base+r)*192 + cc + 64*j] = v;
                    if (j == 0) s_wl0[r*68 + cc] = v;
                }
            }
        }
        __syncthreads();
        // M0 build (+ park to gmem for k_gate)
        int dst;
        {
            int e = rg;
            int src = esrc[base+e]; dst = edst[base+e];
            float ea0 = eattr[(size_t)(base+e)*9];
            float4 xs = *(const float4*)(g_xs + (size_t)src*576 + c0);
            float4 xd = *(const float4*)(g_xd + (size_t)dst*576 + c0);
            float4 wl = *(const float4*)(s_wl0 + e*68 + c0);
            float4 m0;
            m0.x = (xs.x+xd.x)*ea0*wl.x; m0.y = (xs.y+xd.y)*ea0*wl.y;
            m0.z = (xs.z+xd.z)*ea0*wl.z; m0.w = (xs.w+xd.w)*ea0*wl.w;
            *(float4*)(s_M0 + e*68 + c0) = m0;
            *(float4*)(g_m0 + (size_t)(base+e)*64 + c0) = m0;
        }
        __syncthreads();
        // GEMM3: alpha logits (FFMA2)
        {
            unsigned long long q0=0ull,q1=0ull,q2=0ull,q3=0ull;
            const float* Xp = s_M0 + rg*68;
            #pragma unroll 4
            for (int k = 0; k < 64; k += 4){
                ulonglong2 x  = *(const ulonglong2*)(Xp + k);
                ulonglong2 w0 = *(const ulonglong2*)(Wap0 + k);
                ulonglong2 w1 = *(const ulonglong2*)(Wap1 + k);
                ulonglong2 w2 = *(const ulonglong2*)(Wap2 + k);
                ulonglong2 w3 = *(const ulonglong2*)(Wap3 + k);
                ffma2(q0, x.x, w0.x); ffma2(q0, x.y, w0.y);
                ffma2(q1, x.x, w1.x); ffma2(q1, x.y, w1.y);
                ffma2(q2, x.x, w2.x); ffma2(q2, x.y, w2.y);
                ffma2(q3, x.x, w3.x); ffma2(q3, x.y, w3.y);
            }
            float2 p0=up2(q0), p1=up2(q1), p2=up2(q2), p3=up2(q3);
            float4 a;
            a.x = p0.x+p0.y + cb[192+c0  ];
            a.y = p1.x+p1.y + cb[192+c0+1];
            a.z = p2.x+p2.y + cb[192+c0+2];
            a.w = p3.x+p3.y + cb[192+c0+3];
            a.x = 0.2f*a.x + 0.8f*a.x*sigf(a.x);
            a.y = 0.2f*a.y + 0.8f*a.y*sigf(a.y);
            a.z = 0.2f*a.z + 0.8f*a.z*sigf(a.z);
            a.w = 0.2f*a.w + 0.8f*a.w*sigf(a.w);
            float s4 = a.x*cb[256+c0] + a.y*cb[256+c0+1] + a.z*cb[256+c0+2] + a.w*cb[256+c0+3];
            float lg = s4 + __shfl_xor_sync(0xffffffffu, s4, 1);
            if ((tx & 1) == 0){
                int h = tx >> 1;
                g_logit[(size_t)(base+rg)*8 + h] = lg;
                atomicMax(&g_nmax[dst*8 + h], fkey(lg));
            }
        }
    }
}

// ================= K2b: gate = sigmoid(M0 @ Wg + bg) — dense FFMA2 GEMM ========
__global__ __launch_bounds__(256) void k_gate(
    const float* __restrict__ Wv, const float* __restrict__ bv)
{
    extern __shared__ float sm[];
    float* s_Wt = sm;             // [64][68] transposed gate cols
    float* s_X  = s_Wt + 64*68;   // [32][68]
    float* s_b  = s_X + 32*68;    // 64
    int tid = threadIdx.x;
    for (int t = tid; t < 4096; t += 256){
        int k = t>>6, c = t&63;
        s_Wt[c*68 + k] = Wv[k*128 + 64 + c];
    }
    if (tid < 64) s_b[tid] = bv[64 + tid];
    __syncthreads();

    int rgr = tid>>6;     // 0..3
    int cc  = tid&63;
    const float* Wc = s_Wt + cc*68;

    for (int base = blockIdx.x*32; base < NE; base += gridDim.x*32){
        __syncthreads();
        for (int i = tid; i < 512; i += 256){            // float4 staging
            int e = i>>4, c4 = (i&15)*4;
            *(float4*)(s_X + e*68 + c4) = *(const float4*)(g_m0 + (size_t)(base+e)*64 + c4);
        }
        __syncthreads();
        unsigned long long acc[8];
        #pragma unroll
        for (int i = 0; i < 8; i++) acc[i] = 0ull;
        #pragma unroll 4
        for (int k = 0; k < 64; k += 4){
            ulonglong2 w = *(const ulonglong2*)(Wc + k);
            #pragma unroll
            for (int i = 0; i < 8; i++){
                ulonglong2 x = *(const ulonglong2*)(s_X + (rgr + 4*i)*68 + k);
                ffma2(acc[i], x.x, w.x);
                ffma2(acc[i], x.y, w.y);
            }
        }
        float bb = s_b[cc];
        #pragma unroll
        for (int i = 0; i < 8; i++){
            float2 p = up2(acc[i]);
            g_gate[(size_t)(base + rgr + 4*i)*64 + cc] = sigf(p.x + p.y + bb);
        }
    }
}

// ===== K3: value GEMM, FFMA2, PAIR-warp with pair-scoped named barriers ========
// Warp (p,sub) owns cols [32*sub,32*sub+32) (1/lane) and GEMMs BOTH edges of
// pair p (weight stream amortized 2x). Pair-local bar.sync(1+p, 64) replaces
// the block-wide __syncthreads that killed the R9 attempt.
__global__ __launch_bounds__(256, 2) void k_edgeB(
    const float* __restrict__ eattr, const int* __restrict__ esrc,
    const int* __restrict__ edst,    const float* __restrict__ Wv,
    const float* __restrict__ bv)
{
    extern __shared__ float sm[];
    float* s_Wt = sm;                 // [64][68] transposed value cols
    float* s_X  = s_Wt + 64*68;       // [4 pairs][2 edges][9 rows][68]
    float* s_wl = s_X + 4*1224;       // [8][192]
    float* s_ea = s_wl + 8*192;       // [8][12]
    float* s_sw = s_ea + 96;          // [8][8]
    float* s_bv = s_sw + 64;          // 64
    int tid = threadIdx.x;
    for (int t = tid; t < 4096; t += 256){
        int k = t>>6, c = t&63;
        s_Wt[c*68 + k] = Wv[k*128 + c];
    }
    if (tid < 64) s_bv[tid] = bv[tid];
    __syncthreads();

    int w = tid>>5, lane = tid&31;
    int p = w>>1, sub = w&1;
    int col = lane + 32*sub;
    int barid = 1 + p;
    float* pX  = s_X + p*1224;        // pair region
    float* myX = pX + sub*612;        // own edge rows
    float* mywl = s_wl + w*192;
    float* myea = s_ea + w*12;
    float* mysw = s_sw + w*8;
    const float* Wc = s_Wt + col*68;
    float bcol = s_bv[col];

    for (int base = blockIdx.x*8; base < NE; base += 2368){
        int e = base + w;                        // own edge
        int src = esrc[e], dst = edst[e];
        // gates for both pair edges at my column
        float gateA = g_gate[(size_t)(base + 2*p    )*64 + col];
        float gateB = g_gate[(size_t)(base + 2*p + 1)*64 + col];
        // ---- metadata for own edge ----
        #pragma unroll
        for (int t = lane; t < 48; t += 32){
            float4 v = *(const float4*)(g_wlc + (size_t)e*192 + t*4);
            *(float4*)(mywl + t*4) = v;
        }
        if (lane < 9) myea[lane] = eattr[(size_t)e*9 + lane];
        if (lane < 8){
            float lg = g_logit[(size_t)e*8 + lane];
            float mx = fdec(g_nmax[dst*8 + lane]);
            float ww = __expf(lg - mx);
            mysw[lane] = ww;
            atomicAdd(&g_denom[dst*8 + lane], ww);
        }
        __syncwarp();
        // ---- build X for own edge ----
        #pragma unroll
        for (int m = 0; m < 9; m++){
            int lsel = (m==0) ? 0 : (m<4) ? 1 : 2;
            float2 a = *(const float2*)(g_xs + (size_t)src*576 + m*64 + 2*lane);
            float2 b = *(const float2*)(g_xd + (size_t)dst*576 + m*64 + 2*lane);
            float eam = myea[m];
            float2 wl2 = *(const float2*)(mywl + lsel*64 + 2*lane);
            float2 v; v.x = (a.x+b.x)*eam*wl2.x; v.y = (a.y+b.y)*eam*wl2.y;
            *(float2*)(myX + m*68 + 2*lane) = v;
        }
        pbar(barid);                  // build (both warps) done -> GEMM may read
        // ---- pair GEMM: my column, both edges ----
        unsigned long long acc[2][9];
        #pragma unroll
        for (int ee = 0; ee < 2; ee++)
            #pragma unroll
            for (int m = 0; m < 9; m++) acc[ee][m] = 0ull;
        #pragma unroll 4
        for (int k = 0; k < 64; k += 4){
            ulonglong2 wv = *(const ulonglong2*)(Wc + k);
            #pragma unroll
            for (int ee = 0; ee < 2; ee++){
                const float* Xe = pX + ee*612 + k;
                #pragma unroll
                for (int m = 0; m < 9; m++){
                    ulonglong2 x = *(const ulonglong2*)(Xe + m*68);
                    ffma2(acc[ee][m], x.x, wv.x);
                    ffma2(acc[ee][m], x.y, wv.y);
                }
            }
        }
        pbar(barid);                  // GEMM reads done -> epilogue may overwrite
        // ---- epilogue: postprocess both edges at my column ----
        #pragma unroll
        for (int ee = 0; ee < 2; ee++){
            int el = 2*p + ee;
            float gate = ee ? gateB : gateA;
            float wh = s_sw[el*8 + (col>>3)];
            #pragma unroll
            for (int m = 0; m < 9; m++){
                int lsel = (m==0) ? 0 : (m<4) ? 1 : 2;
                float2 v = up2(acc[ee][m]);
                float y = v.x + v.y;
                float o;
                if (m == 0){ y += bcol; o = y * sigf(y); }
                else        { o = y * gate; }
                o *= s_ea[el*12 + m] * s_wl[el*192 + lsel*64 + col] * wh;
                pX[ee*612 + m*68 + col] = o;
            }
        }
        pbar(barid);                  // epilogue (both warps) visible -> scatter
        // ---- float4 atomic scatter of own edge ----
        float* accp = g_acc + (size_t)dst*576;
        #pragma unroll
        for (int t = lane; t < 144; t += 32){
            int r = t>>4, c4 = (t&15)*4;
            float4 v = *(const float4*)(myX + r*68 + c4);
            atomicAdd((float4*)(accp + r*64 + c4), v);
        }
        // no trailing barrier needed: between here and the next post-build
        // barrier, only this warp touches its own rows/metadata; the partner's
        // reads of them (epilogue of this iter) completed before barrier 3.
    }
}

// ================= K4: normalize + projection (8 nodes/iter) ====================
__global__ __launch_bounds__(256) void k_out(
    const float* __restrict__ Wp, const float* __restrict__ bp, float* __restrict__ out)
{
    extern __shared__ float sm[];
    float* s_W  = sm;              // [64][68]
    float* s_X  = s_W + 64*68;     // [80][68]
    float* s_b  = s_X + 80*68;     // 64
    float* s_inv= s_b + 64;        // 64
    int tid = threadIdx.x;
    for (int t = tid; t < 4096; t += 256){
        int k = t>>6, j = t&63;
        s_W[k*68 + j] = Wp[t];
    }
    if (tid < 64) s_b[tid] = bp[tid];
    for (int t = tid; t < 8*68; t += 256) s_X[72*68 + t] = 0.f;
    __syncthreads();

    int rg = tid>>4, tx = tid&15, c0 = tx*4, r0 = rg*5;

    for (int base = blockIdx.x*8; base < NN; base += gridDim.x*8){
        __syncthreads();
        if (tid < 64){
            int e = tid>>3, h = tid&7;
            s_inv[tid] = 1.f/(g_denom[(base+e)*8 + h] + 1e-16f);
        }
        __syncthreads();
        for (int i = tid; i < 8*576; i += 256){
            int n = i/576, rem = i - n*576;
            int row = n*9 + (rem>>6), col = rem&63;
            s_X[row*68 + col] = g_acc[(size_t)(base+n)*576 + rem] * s_inv[n*8 + (col>>3)];
        }
        __syncthreads();
        float4 a0 = {0,0,0,0}, a1 = a0, a2 = a0, a3 = a0, a4 = a0;
        const float* Xp = s_X + r0*68;
        #pragma unroll 4
        for (int k = 0; k < 64; k += 4){
            float4 w0 = *(const float4*)(s_W + (k  )*68 + c0);
            float4 w1 = *(const float4*)(s_W + (k+1)*68 + c0);
            float4 w2 = *(const float4*)(s_W + (k+2)*68 + c0);
            float4 w3 = *(const float4*)(s_W + (k+3)*68 + c0);
            float4 x0 = *(const float4*)(Xp + k);
            float4 x1 = *(const float4*)(Xp + 68 + k);
            float4 x2 = *(const float4*)(Xp + 136 + k);
            float4 x3 = *(const float4*)(Xp + 204 + k);
            float4 x4 = *(const float4*)(Xp + 272 + k);
            a0.x += x0.x*w0.x + x0.y*w1.x + x0.z*w2.x + x0.w*w3.x;
            a0.y += x0.x*w0.y + x0.y*w1.y + x0.z*w2.y + x0.w*w3.y;
            a0.z += x0.x*w0.z + x0.y*w1.z + x0.z*w2.z + x0.w*w3.z;
            a0.w += x0.x*w0.w + x0.y*w1.w + x0.z*w2.w + x0.w*w3.w;
            a1.x += x1.x*w0.x + x1.y*w1.x + x1.z*w2.x + x1.w*w3.x;
            a1.y += x1.x*w0.y + x1.y*w1.y + x1.z*w2.y + x1.w*w3.y;
            a1.z += x1.x*w0.z + x1.y*w1.z + x1.z*w2.z + x1.w*w3.z;
            a1.w += x1.x*w0.w + x1.y*w1.w + x1.z*w2.w + x1.w*w3.w;
            a2.x += x2.x*w0.x + x2.y*w1.x + x2.z*w2.x + x2.w*w3.x;
            a2.y += x2.x*w0.y + x2.y*w1.y + x2.z*w2.y + x2.w*w3.y;
            a2.z += x2.x*w0.z + x2.y*w1.z + x2.z*w2.z + x2.w*w3.z;
            a2.w += x2.x*w0.w + x2.y*w1.w + x2.z*w2.w + x2.w*w3.w;
            a3.x += x3.x*w0.x + x3.y*w1.x + x3.z*w2.x + x3.w*w3.x;
            a3.y += x3.x*w0.y + x3.y*w1.y + x3.z*w2.y + x3.w*w3.y;
            a3.z += x3.x*w0.z + x3.y*w1.z + x3.z*w2.z + x3.w*w3.z;
            a3.w += x3.x*w0.w + x3.y*w1.w + x3.z*w2.w + x3.w*w3.w;
            a4.x += x4.x*w0.x + x4.y*w1.x + x4.z*w2.x + x4.w*w3.x;
            a4.y += x4.x*w0.y + x4.y*w1.y + x4.z*w2.y + x4.w*w3.y;
            a4.z += x4.x*w0.z + x4.y*w1.z + x4.z*w2.z + x4.w*w3.z;
            a4.w += x4.x*w0.w + x4.y*w1.w + x4.z*w2.w + x4.w*w3.w;
        }
        float4 acc[5] = {a0,a1,a2,a3,a4};
        #pragma unroll
        for (int i = 0; i < 5; i++){
            int r = r0 + i;
            if (r < 72){
                int n = base + r/9, m = r%9;
                float4 v = acc[i];
                if (m == 0){
                    v.x += s_b[c0]; v.y += s_b[c0+1]; v.z += s_b[c0+2]; v.w += s_b[c0+3];
                }
                *(float4*)(out + (size_t)n*576 + m*64 + c0) = v;
            }
        }
    }
}

extern "C" void kernel_launch(void* const* d_in, const int* in_sizes, int n_in,
                              void* d_out, int out_size)
{
    const float* node_input = (const float*)d_in[0];
    const float* edge_attr  = (const float*)d_in[1];
    const float* edge_scal  = (const float*)d_in[2];
    const float* W_src = (const float*)d_in[3];
    const float* b_src = (const float*)d_in[4];
    const float* W_dst = (const float*)d_in[5];
    const float* rW1   = (const float*)d_in[6];
    const float* rb1   = (const float*)d_in[7];
    const float* lng   = (const float*)d_in[8];
    const float* lnb   = (const float*)d_in[9];
    const float* rW2   = (const float*)d_in[10];
    const float* roff  = (const float*)d_in[11];
    const float* Wa    = (const float*)d_in[12];
    const float* ba    = (const float*)d_in[13];
    const float* adot  = (const float*)d_in[14];
    const float* Wv    = (const float*)d_in[15];
    const float* bv    = (const float*)d_in[16];
    const float* Wp    = (const float*)d_in[17];
    const float* bp    = (const float*)d_in[18];
    const int*   esrc  = (const int*)d_in[19];
    const int*   edst  = (const int*)d_in[20];
    float* out = (float*)d_out;

    const int smem_node = (64*128 + 40*68 + 64) * 4;
    const int smem_eA   = (64*68*2 + 192*68 + 512 + 16*68*4) * 4;   // ~106.5 KB
    const int smem_gate = (64*68 + 32*68 + 64) * 4;
    const int smem_eB   = (64*68 + 4*1224 + 8*192 + 96 + 64 + 64) * 4;
    const int smem_out  = (64*68 + 80*68 + 64 + 64) * 4;

    cudaFuncSetAttribute(k_node,  cudaFuncAttributeMaxDynamicSharedMemorySize, smem_node);
    cudaFuncSetAttribute(k_edgeA, cudaFuncAttributeMaxDynamicSharedMemorySize, smem_eA);
    cudaFuncSetAttribute(k_gate,  cudaFuncAttributeMaxDynamicSharedMemorySize, smem_gate);
    cudaFuncSetAttribute(k_edgeB, cudaFuncAttributeMaxDynamicSharedMemorySize, smem_eB);
    cudaFuncSetAttribute(k_out,   cudaFuncAttributeMaxDynamicSharedMemorySize, smem_out);

    k_init<<<2048, 256>>>();
    k_node<<<296, 256, smem_node>>>(node_input, W_src, b_src, W_dst);
    k_edgeA<<<296, 256, smem_eA>>>(edge_scal, edge_attr, esrc, edst,
                                   rW1, rb1, lng, lnb, rW2, roff, Wa, ba, adot);
    k_gate<<<592, 256, smem_gate>>>(Wv, bv);
    k_edgeB<<<296, 256, smem_eB>>>(edge_attr, esrc, edst, Wv, bv);
    k_out<<<296, 256, smem_out>>>(Wp, bp, out);
}

// round 12
// speedup vs baseline: 1.1810x; 1.1810x over previous
#include <cuda_runtime.h>
#include <math.h>

#define NN 10000
#define NE 160000
#define MM 9
#define CC 64
#define HH 8

// ---------------- scratch (static device globals; no allocation) ----------------
__device__ float    g_xs[NN*MM*CC];        // node src-linear   (23 MB)
__device__ float    g_xd[NN*MM*CC];        // node dst-linear   (23 MB)
__device__ float    g_wlc[(size_t)NE*192]; // radial weights    (123 MB)
__device__ float    g_m0[(size_t)NE*64];   // msg row 0         (41 MB)
__device__ float    g_gate[(size_t)NE*64]; // sigmoid(gate)     (41 MB)
__device__ float    g_logit[NE*HH];
__device__ unsigned g_nmax[NN*HH];         // monotone-mapped float max
__device__ float    g_denom[NN*HH];
__device__ float    g_acc[NN*MM*CC];

__device__ __forceinline__ unsigned fkey(float f){
    int i = __float_as_int(f);
    return (i >= 0) ? ((unsigned)i ^ 0x80000000u) : ~(unsigned)i;
}
__device__ __forceinline__ float fdec(unsigned u){
    int i = (u & 0x80000000u) ? (int)(u ^ 0x80000000u) : (int)(~u);
    return __int_as_float(i);
}
__device__ __forceinline__ float sigf(float x){ return 1.f/(1.f + __expf(-x)); }

// packed fp32x2 FMA: d = a*b + d
__device__ __forceinline__ void ffma2(unsigned long long& d,
                                      unsigned long long a,
                                      unsigned long long b){
    asm("fma.rn.f32x2 %0, %1, %2, %0;" : "+l"(d) : "l"(a), "l"(b));
}
__device__ __forceinline__ float2 up2(unsigned long long v){
    float2 r; asm("mov.b64 {%0,%1}, %2;" : "=f"(r.x), "=f"(r.y) : "l"(v)); return r;
}

__global__ void k_init(){
    int i = blockIdx.x*blockDim.x + threadIdx.x;
    int st = gridDim.x*blockDim.x;
    for (int t = i; t < NN*MM*CC; t += st) g_acc[t] = 0.f;
    for (int t = i; t < NN*HH;    t += st){ g_denom[t] = 0.f; g_nmax[t] = fkey(-INFINITY); }
}

// ================= K1: node linear (GEMM: 4 nodes -> X[40x64] @ W[64x128]) =====
__global__ __launch_bounds__(256) void k_node(
    const float* __restrict__ xin, const float* __restrict__ Ws,
    const float* __restrict__ bs,  const float* __restrict__ Wd)
{
    extern __shared__ float sm[];
    float* s_W = sm;               // [64][128]
    float* s_X = s_W + 64*128;     // [40][68]
    float* s_b = s_X + 40*68;      // 64
    int tid = threadIdx.x;
    for (int t = tid; t < 8192; t += 256){
        int k = t>>7, c = t&127;
        s_W[t] = (c < 64) ? Ws[k*64 + c] : Wd[k*64 + (c-64)];
    }
    if (tid < 64) s_b[tid] = bs[tid];
    for (int t = tid; t < 4*68; t += 256) s_X[36*68 + t] = 0.f;
    __syncthreads();

    int rg = tid>>5;
    int c0 = (tid&31)*4;
    int r0 = rg*5;

    for (int base = blockIdx.x*4; base < NN; base += gridDim.x*4){
        __syncthreads();
        // float4 staging: 4 nodes x 576 floats = 576 float4
        for (int i = tid; i < 576; i += 256){
            int n = i/144, rem = i - n*144;       // rem in float4 units
            int row = n*9 + (rem>>4), c4 = (rem&15)*4;
            *(float4*)(s_X + row*68 + c4) =
                *(const float4*)(xin + (size_t)(base+n)*576 + (rem>>4)*64 + c4);
        }
        __syncthreads();
        float4 a0 = {0,0,0,0}, a1 = a0, a2 = a0, a3 = a0, a4 = a0;
        const float* Xp = s_X + r0*68;
        #pragma unroll 4
        for (int k = 0; k < 64; k += 4){
            float4 w0 = *(const float4*)(s_W + (k  )*128 + c0);
            float4 w1 = *(const float4*)(s_W + (k+1)*128 + c0);
            float4 w2 = *(const float4*)(s_W + (k+2)*128 + c0);
            float4 w3 = *(const float4*)(s_W + (k+3)*128 + c0);
            float4 x0 = *(const float4*)(Xp + k);
            float4 x1 = *(const float4*)(Xp + 68 + k);
            float4 x2 = *(const float4*)(Xp + 136 + k);
            float4 x3 = *(const float4*)(Xp + 204 + k);
            float4 x4 = *(const float4*)(Xp + 272 + k);
            a0.x += x0.x*w0.x + x0.y*w1.x + x0.z*w2.x + x0.w*w3.x;
            a0.y += x0.x*w0.y + x0.y*w1.y + x0.z*w2.y + x0.w*w3.y;
            a0.z += x0.x*w0.z + x0.y*w1.z + x0.z*w2.z + x0.w*w3.z;
            a0.w += x0.x*w0.w + x0.y*w1.w + x0.z*w2.w + x0.w*w3.w;
            a1.x += x1.x*w0.x + x1.y*w1.x + x1.z*w2.x + x1.w*w3.x;
            a1.y += x1.x*w0.y + x1.y*w1.y + x1.z*w2.y + x1.w*w3.y;
            a1.z += x1.x*w0.z + x1.y*w1.z + x1.z*w2.z + x1.w*w3.z;
            a1.w += x1.x*w0.w + x1.y*w1.w + x1.z*w2.w + x1.w*w3.w;
            a2.x += x2.x*w0.x + x2.y*w1.x + x2.z*w2.x + x2.w*w3.x;
            a2.y += x2.x*w0.y + x2.y*w1.y + x2.z*w2.y + x2.w*w3.y;
            a2.z += x2.x*w0.z + x2.y*w1.z + x2.z*w2.z + x2.w*w3.z;
            a2.w += x2.x*w0.w + x2.y*w1.w + x2.z*w2.w + x2.w*w3.w;
            a3.x += x3.x*w0.x + x3.y*w1.x + x3.z*w2.x + x3.w*w3.x;
            a3.y += x3.x*w0.y + x3.y*w1.y + x3.z*w2.y + x3.w*w3.y;
            a3.z += x3.x*w0.z + x3.y*w1.z + x3.z*w2.z + x3.w*w3.z;
            a3.w += x3.x*w0.w + x3.y*w1.w + x3.z*w2.w + x3.w*w3.w;
            a4.x += x4.x*w0.x + x4.y*w1.x + x4.z*w2.x + x4.w*w3.x;
            a4.y += x4.x*w0.y + x4.y*w1.y + x4.z*w2.y + x4.w*w3.y;
            a4.z += x4.x*w0.z + x4.y*w1.z + x4.z*w2.z + x4.w*w3.z;
            a4.w += x4.x*w0.w + x4.y*w1.w + x4.z*w2.w + x4.w*w3.w;
        }
        float4 acc[5] = {a0,a1,a2,a3,a4};
        #pragma unroll
        for (int i = 0; i < 5; i++){
            int r = r0 + i;
            if (r < 36){
                int n = base + r/9, m = r%9;
                float4 v = acc[i];
                if (m == 0 && c0 < 64){
                    v.x += s_b[c0]; v.y += s_b[c0+1]; v.z += s_b[c0+2]; v.w += s_b[c0+3];
                }
                if (c0 < 64) *(float4*)(g_xs + (size_t)n*576 + m*64 + c0) = v;
                else         *(float4*)(g_xd + (size_t)n*576 + m*64 + (c0-64)) = v;
            }
        }
    }
}

// ===== K2: radial MLP + alpha logits, FFMA2 (16 edges/iter, 256t) ===============
__global__ __launch_bounds__(256) void k_edgeA(
    const float* __restrict__ esc, const float* __restrict__ eattr,
    const int* __restrict__ esrc,  const int* __restrict__ edst,
    const float* __restrict__ W1,  const float* __restrict__ b1,
    const float* __restrict__ lng, const float* __restrict__ lnb,
    const float* __restrict__ W2,  const float* __restrict__ off,
    const float* __restrict__ Wa,  const float* __restrict__ ba,
    const float* __restrict__ adot)
{
    extern __shared__ float sm[];
    float* s_W1T = sm;                // [64 slots][68]
    float* s_WaT = s_W1T + 64*68;     // [64 slots][68]
    float* s_W2T = s_WaT + 64*68;     // [192 cols][68]
    float* cb    = s_W2T + 192*68;    // b1|lng|lnb|ba|adot|off = 512
    float* s_S   = cb + 512;          // [16][68]
    float* s_H   = s_S + 16*68;       // [16][68]
    float* s_M0  = s_H + 16*68;       // [16][68]
    float* s_wl0 = s_M0 + 16*68;      // [16][68]
    int tid = threadIdx.x;
    for (int t = tid; t < 4096; t += 256){
        int k = t>>6, j = t&63;
        int slot = (j&3)*16 + (j>>2);
        s_W1T[slot*68 + k] = W1[t];
        s_WaT[slot*68 + k] = Wa[t];
    }
    for (int t = tid; t < 12288; t += 256){
        int k = t/192, c = t - k*192;
        s_W2T[c*68 + k] = W2[t];
    }
    if (tid < 64){
        cb[tid] = b1[tid]; cb[64+tid] = lng[tid]; cb[128+tid] = lnb[tid];
        cb[192+tid] = ba[tid]; cb[256+tid] = adot[tid];
    }
    for (int t = tid; t < 192; t += 256) cb[320+t] = off[t];
    __syncthreads();

    int rg = tid>>4;            // 0..15 (edge row)
    int tx = tid&15;
    int c0 = tx*4;
    const float* W1p0 = s_W1T + tx*68;
    const float* W1p1 = s_W1T + (tx+16)*68;
    const float* W1p2 = s_W1T + (tx+32)*68;
    const float* W1p3 = s_W1T + (tx+48)*68;
    const float* Wap0 = s_WaT + tx*68;
    const float* Wap1 = s_WaT + (tx+16)*68;
    const float* Wap2 = s_WaT + (tx+32)*68;
    const float* Wap3 = s_WaT + (tx+48)*68;

    for (int base = blockIdx.x*16; base < NE; base += gridDim.x*16){
        __syncthreads();
        for (int i = tid; i < 256; i += 256){ }
        for (int i = tid; i < 16*16; i += 256){       // float4 staging of scalars
            int e = i>>4, c4 = (i&15)*4;
            *(float4*)(s_S + e*68 + c4) = *(const float4*)(esc + (size_t)(base+e)*64 + c4);
        }
        __syncthreads();
        // GEMM1: H = S @ W1  (FFMA2)
        {
            unsigned long long q0=0ull,q1=0ull,q2=0ull,q3=0ull;
            const float* Xp = s_S + rg*68;
            #pragma unroll 4
            for (int k = 0; k < 64; k += 4){
                ulonglong2 x  = *(const ulonglong2*)(Xp + k);
                ulonglong2 w0 = *(const ulonglong2*)(W1p0 + k);
                ulonglong2 w1 = *(const ulonglong2*)(W1p1 + k);
                ulonglong2 w2 = *(const ulonglong2*)(W1p2 + k);
                ulonglong2 w3 = *(const ulonglong2*)(W1p3 + k);
                ffma2(q0, x.x, w0.x); ffma2(q0, x.y, w0.y);
                ffma2(q1, x.x, w1.x); ffma2(q1, x.y, w1.y);
                ffma2(q2, x.x, w2.x); ffma2(q2, x.y, w2.y);
                ffma2(q3, x.x, w3.x); ffma2(q3, x.y, w3.y);
            }
            float2 p0=up2(q0), p1=up2(q1), p2=up2(q2), p3=up2(q3);
            float4 a;
            a.x = p0.x+p0.y + cb[c0  ];
            a.y = p1.x+p1.y + cb[c0+1];
            a.z = p2.x+p2.y + cb[c0+2];
            a.w = p3.x+p3.y + cb[c0+3];
            float s = a.x+a.y+a.z+a.w;
            float q = a.x*a.x+a.y*a.y+a.z*a.z+a.w*a.w;
            #pragma unroll
            for (int o = 8; o > 0; o >>= 1){
                s += __shfl_xor_sync(0xffffffffu, s, o);
                q += __shfl_xor_sync(0xffffffffu, q, o);
            }
            float mu = s*(1.f/64.f);
            float var = q*(1.f/64.f) - mu*mu;
            float rs = rsqrtf(var + 1e-5f);
            float4 h;
            h.x = (a.x-mu)*rs*cb[64+c0  ] + cb[128+c0  ];
            h.y = (a.y-mu)*rs*cb[64+c0+1] + cb[128+c0+1];
            h.z = (a.z-mu)*rs*cb[64+c0+2] + cb[128+c0+2];
            h.w = (a.w-mu)*rs*cb[64+c0+3] + cb[128+c0+3];
            h.x *= sigf(h.x); h.y *= sigf(h.y); h.z *= sigf(h.z); h.w *= sigf(h.w);
            *(float4*)(s_H + rg*68 + c0) = h;
        }
        __syncthreads();
        // GEMM2: WL = H @ W2  (FFMA2, write g_wlc directly, stash wl0)
        {
            int rgr = tid>>6;
            int cc  = tid&63;
            unsigned long long acc[4][3];
            #pragma unroll
            for (int i = 0; i < 4; i++){ acc[i][0]=0ull; acc[i][1]=0ull; acc[i][2]=0ull; }
            const float* Wp0 = s_W2T + cc*68;
            const float* Wp1 = s_W2T + (cc+64)*68;
            const float* Wp2 = s_W2T + (cc+128)*68;
            #pragma unroll 4
            for (int k = 0; k < 64; k += 4){
                ulonglong2 w0 = *(const ulonglong2*)(Wp0 + k);
                ulonglong2 w1 = *(const ulonglong2*)(Wp1 + k);
                ulonglong2 w2 = *(const ulonglong2*)(Wp2 + k);
                ulonglong2 x0 = *(const ulonglong2*)(s_H + (rgr   )*68 + k);
                ulonglong2 x1 = *(const ulonglong2*)(s_H + (rgr+4 )*68 + k);
                ulonglong2 x2 = *(const ulonglong2*)(s_H + (rgr+8 )*68 + k);
                ulonglong2 x3 = *(const ulonglong2*)(s_H + (rgr+12)*68 + k);
                ffma2(acc[0][0], x0.x, w0.x); ffma2(acc[0][0], x0.y, w0.y);
                ffma2(acc[0][1], x0.x, w1.x); ffma2(acc[0][1], x0.y, w1.y);
                ffma2(acc[0][2], x0.x, w2.x); ffma2(acc[0][2], x0.y, w2.y);
                ffma2(acc[1][0], x1.x, w0.x); ffma2(acc[1][0], x1.y, w0.y);
                ffma2(acc[1][1], x1.x, w1.x); ffma2(acc[1][1], x1.y, w1.y);
                ffma2(acc[1][2], x1.x, w2.x); ffma2(acc[1][2], x1.y, w2.y);
                ffma2(acc[2][0], x2.x, w0.x); ffma2(acc[2][0], x2.y, w0.y);
                ffma2(acc[2][1], x2.x, w1.x); ffma2(acc[2][1], x2.y, w1.y);
                ffma2(acc[2][2], x2.x, w2.x); ffma2(acc[2][2], x2.y, w2.y);
                ffma2(acc[3][0], x3.x, w0.x); ffma2(acc[3][0], x3.y, w0.y);
                ffma2(acc[3][1], x3.x, w1.x); ffma2(acc[3][1], x3.y, w1.y);
                ffma2(acc[3][2], x3.x, w2.x); ffma2(acc[3][2], x3.y, w2.y);
            }
            #pragma unroll
            for (int i = 0; i < 4; i++){
                int r = rgr + i*4;
                #pragma unroll
                for (int j = 0; j < 3; j++){
                    float2 p = up2(acc[i][j]);
                    float v = p.x + p.y + cb[320 + cc + 64*j];
                    g_wlc[(size_t)(base+r)*192 + cc + 64*j] = v;
                    if (j == 0) s_wl0[r*68 + cc] = v;
                }
            }
        }
        __syncthreads();
        // M0 build (+ park to gmem for k_gate)
        int dst;
        {
            int e = rg;
            int src = esrc[base+e]; dst = edst[base+e];
            float ea0 = eattr[(size_t)(base+e)*9];
            float4 xs = *(const float4*)(g_xs + (size_t)src*576 + c0);
            float4 xd = *(const float4*)(g_xd + (size_t)dst*576 + c0);
            float4 wl = *(const float4*)(s_wl0 + e*68 + c0);
            float4 m0;
            m0.x = (xs.x+xd.x)*ea0*wl.x; m0.y = (xs.y+xd.y)*ea0*wl.y;
            m0.z = (xs.z+xd.z)*ea0*wl.z; m0.w = (xs.w+xd.w)*ea0*wl.w;
            *(float4*)(s_M0 + e*68 + c0) = m0;
            *(float4*)(g_m0 + (size_t)(base+e)*64 + c0) = m0;
        }
        __syncthreads();
        // GEMM3: alpha logits (FFMA2)
        {
            unsigned long long q0=0ull,q1=0ull,q2=0ull,q3=0ull;
            const float* Xp = s_M0 + rg*68;
            #pragma unroll 4
            for (int k = 0; k < 64; k += 4){
                ulonglong2 x  = *(const ulonglong2*)(Xp + k);
                ulonglong2 w0 = *(const ulonglong2*)(Wap0 + k);
                ulonglong2 w1 = *(const ulonglong2*)(Wap1 + k);
                ulonglong2 w2 = *(const ulonglong2*)(Wap2 + k);
                ulonglong2 w3 = *(const ulonglong2*)(Wap3 + k);
                ffma2(q0, x.x, w0.x); ffma2(q0, x.y, w0.y);
                ffma2(q1, x.x, w1.x); ffma2(q1, x.y, w1.y);
                ffma2(q2, x.x, w2.x); ffma2(q2, x.y, w2.y);
                ffma2(q3, x.x, w3.x); ffma2(q3, x.y, w3.y);
            }
            float2 p0=up2(q0), p1=up2(q1), p2=up2(q2), p3=up2(q3);
            float4 a;
            a.x = p0.x+p0.y + cb[192+c0  ];
            a.y = p1.x+p1.y + cb[192+c0+1];
            a.z = p2.x+p2.y + cb[192+c0+2];
            a.w = p3.x+p3.y + cb[192+c0+3];
            a.x = 0.2f*a.x + 0.8f*a.x*sigf(a.x);
            a.y = 0.2f*a.y + 0.8f*a.y*sigf(a.y);
            a.z = 0.2f*a.z + 0.8f*a.z*sigf(a.z);
            a.w = 0.2f*a.w + 0.8f*a.w*sigf(a.w);
            float s4 = a.x*cb[256+c0] + a.y*cb[256+c0+1] + a.z*cb[256+c0+2] + a.w*cb[256+c0+3];
            float lg = s4 + __shfl_xor_sync(0xffffffffu, s4, 1);
            if ((tx & 1) == 0){
                int h = tx >> 1;
                g_logit[(size_t)(base+rg)*8 + h] = lg;
                atomicMax(&g_nmax[dst*8 + h], fkey(lg));
            }
        }
    }
}

// ================= K2b: gate = sigmoid(M0 @ Wg + bg) — dense FFMA2 GEMM ========
__global__ __launch_bounds__(256) void k_gate(
    const float* __restrict__ Wv, const float* __restrict__ bv)
{
    extern __shared__ float sm[];
    float* s_Wt = sm;             // [64][68] transposed gate cols
    float* s_X  = s_Wt + 64*68;   // [32][68]
    float* s_b  = s_X + 32*68;    // 64
    int tid = threadIdx.x;
    for (int t = tid; t < 4096; t += 256){
        int k = t>>6, c = t&63;
        s_Wt[c*68 + k] = Wv[k*128 + 64 + c];
    }
    if (tid < 64) s_b[tid] = bv[64 + tid];
    __syncthreads();

    int rgr = tid>>6;     // 0..3
    int cc  = tid&63;
    const float* Wc = s_Wt + cc*68;

    for (int base = blockIdx.x*32; base < NE; base += gridDim.x*32){
        __syncthreads();
        for (int i = tid; i < 512; i += 256){            // float4 staging
            int e = i>>4, c4 = (i&15)*4;
            *(float4*)(s_X + e*68 + c4) = *(const float4*)(g_m0 + (size_t)(base+e)*64 + c4);
        }
        __syncthreads();
        unsigned long long acc[8];
        #pragma unroll
        for (int i = 0; i < 8; i++) acc[i] = 0ull;
        #pragma unroll 4
        for (int k = 0; k < 64; k += 4){
            ulonglong2 w = *(const ulonglong2*)(Wc + k);
            #pragma unroll
            for (int i = 0; i < 8; i++){
                ulonglong2 x = *(const ulonglong2*)(s_X + (rgr + 4*i)*68 + k);
                ffma2(acc[i], x.x, w.x);
                ffma2(acc[i], x.y, w.y);
            }
        }
        float bb = s_b[cc];
        #pragma unroll
        for (int i = 0; i < 8; i++){
            float2 p = up2(acc[i]);
            g_gate[(size_t)(base + rgr + 4*i)*64 + cc] = sigf(p.x + p.y + bb);
        }
    }
}

// ================= K3: value GEMM + weighted scatter, FFMA2, warp-per-edge ======
__global__ __launch_bounds__(256, 2) void k_edgeB(
    const float* __restrict__ eattr, const int* __restrict__ esrc,
    const int* __restrict__ edst,    const float* __restrict__ Wv,
    const float* __restrict__ bv)
{
    extern __shared__ float sm[];
    float* s_Wt = sm;                 // [64][68] transposed value cols
    float* s_X  = s_Wt + 64*68;       // [8 warps][9 rows][68]
    float* s_wl = s_X + 8*9*68;       // [8][192]
    float* s_ea = s_wl + 8*192;       // [8][12]
    float* s_sw = s_ea + 96;          // [8][8]
    float* s_bv = s_sw + 64;          // 64
    int tid = threadIdx.x;
    for (int t = tid; t < 4096; t += 256){
        int k = t>>6, c = t&63;
        s_Wt[c*68 + k] = Wv[k*128 + c];
    }
    if (tid < 64) s_bv[tid] = bv[tid];
    __syncthreads();

    int w = tid>>5, lane = tid&31;
    float* myX  = s_X  + w*9*68;
    float* mywl = s_wl + w*192;
    float* myea = s_ea + w*12;
    float* mysw = s_sw + w*8;
    const float* Wc0 = s_Wt + lane*68;
    const float* Wc1 = s_Wt + (lane+32)*68;
    int gw = blockIdx.x*8 + w;

    for (int e = gw; e < NE; e += 2368){
        int src = esrc[e], dst = edst[e];
        float gate0 = g_gate[(size_t)e*64 + lane];
        float gate1 = g_gate[(size_t)e*64 + lane + 32];
        #pragma unroll
        for (int t = lane; t < 48; t += 32){
            float4 v = *(const float4*)(g_wlc + (size_t)e*192 + t*4);
            *(float4*)(mywl + t*4) = v;
        }
        if (lane < 9) myea[lane] = eattr[(size_t)e*9 + lane];
        if (lane < 8){
            float lg = g_logit[(size_t)e*8 + lane];
            float mx = fdec(g_nmax[dst*8 + lane]);
            float ww = __expf(lg - mx);
            mysw[lane] = ww;
            atomicAdd(&g_denom[dst*8 + lane], ww);
        }
        __syncwarp();
        #pragma unroll
        for (int m = 0; m < 9; m++){
            int lsel = (m==0) ? 0 : (m<4) ? 1 : 2;
            float2 a = *(const float2*)(g_xs + (size_t)src*576 + m*64 + 2*lane);
            float2 b = *(const float2*)(g_xd + (size_t)dst*576 + m*64 + 2*lane);
            float eam = myea[m];
            float2 wl2 = *(const float2*)(mywl + lsel*64 + 2*lane);
            float2 v; v.x = (a.x+b.x)*eam*wl2.x; v.y = (a.y+b.y)*eam*wl2.y;
            *(float2*)(myX + m*68 + 2*lane) = v;
        }
        __syncwarp();
        unsigned long long accv[9][2];
        #pragma unroll
        for (int m = 0; m < 9; m++){ accv[m][0] = 0ull; accv[m][1] = 0ull; }
        #pragma unroll 4
        for (int k = 0; k < 64; k += 4){
            ulonglong2 w0 = *(const ulonglong2*)(Wc0 + k);
            ulonglong2 w1 = *(const ulonglong2*)(Wc1 + k);
            #pragma unroll
            for (int m = 0; m < 9; m++){
                ulonglong2 x = *(const ulonglong2*)(myX + m*68 + k);
                ffma2(accv[m][0], x.x, w0.x); ffma2(accv[m][0], x.y, w0.y);
                ffma2(accv[m][1], x.x, w1.x); ffma2(accv[m][1], x.y, w1.y);
            }
        }
        __syncwarp();
        {
            float whA = mysw[lane>>3];
            float whB = mysw[(lane+32)>>3];
            #pragma unroll
            for (int m = 0; m < 9; m++){
                int lsel = (m==0) ? 0 : (m<4) ? 1 : 2;
                float2 vA = up2(accv[m][0]);
                float2 vB = up2(accv[m][1]);
                float yA = vA.x + vA.y;
                float yB = vB.x + vB.y;
                float oA, oB;
                if (m == 0){
                    yA += s_bv[lane]; yB += s_bv[lane+32];
                    oA = yA * sigf(yA); oB = yB * sigf(yB);
                } else {
                    oA = yA * gate0; oB = yB * gate1;
                }
                float eam = myea[m];
                oA *= eam * mywl[lsel*64 + lane]      * whA;
                oB *= eam * mywl[lsel*64 + lane + 32] * whB;
                myX[m*68 + lane]      = oA;
                myX[m*68 + lane + 32] = oB;
            }
        }
        __syncwarp();
        float* accp = g_acc + (size_t)dst*576;
        #pragma unroll
        for (int t = lane; t < 144; t += 32){
            int r = t>>4, c4 = (t&15)*4;
            float4 v = *(const float4*)(myX + r*68 + c4);
            atomicAdd((float4*)(accp + r*64 + c4), v);
        }
        __syncwarp();
    }
}

// ================= K4: normalize + projection (8 nodes/iter) ====================
__global__ __launch_bounds__(256) void k_out(
    const float* __restrict__ Wp, const float* __restrict__ bp, float* __restrict__ out)
{
    extern __shared__ float sm[];
    float* s_W  = sm;              // [64][68]
    float* s_X  = s_W + 64*68;     // [80][68]
    float* s_b  = s_X + 80*68;     // 64
    float* s_inv= s_b + 64;        // 64
    int tid = threadIdx.x;
    for (int t = tid; t < 4096; t += 256){
        int k = t>>6, j = t&63;
        s_W[k*68 + j] = Wp[t];
    }
    if (tid < 64) s_b[tid] = bp[tid];
    for (int t = tid; t < 8*68; t += 256) s_X[72*68 + t] = 0.f;
    __syncthreads();

    int rg = tid>>4, tx = tid&15, c0 = tx*4, r0 = rg*5;

    for (int base = blockIdx.x*8; base < NN; base += gridDim.x*8){
        __syncthreads();
        if (tid < 64){
            int e = tid>>3, h = tid&7;
            s_inv[tid] = 1.f/(g_denom[(base+e)*8 + h] + 1e-16f);
        }
        __syncthreads();
        // float4 staging: 8 nodes x 144 float4
        for (int i = tid; i < 1152; i += 256){
            int n = i/144, rem = i - n*144;
            int row = n*9 + (rem>>4), c4 = (rem&15)*4;
            float inv = s_inv[n*8 + (c4>>3)];
            float4 v = *(const float4*)(g_acc + (size_t)(base+n)*576 + (rem>>4)*64 + c4);
            v.x *= inv; v.y *= inv; v.z *= inv; v.w *= inv;
            *(float4*)(s_X + row*68 + c4) = v;
        }
        __syncthreads();
        float4 a0 = {0,0,0,0}, a1 = a0, a2 = a0, a3 = a0, a4 = a0;
        const float* Xp = s_X + r0*68;
        #pragma unroll 4
        for (int k = 0; k < 64; k += 4){
            float4 w0 = *(const float4*)(s_W + (k  )*68 + c0);
            float4 w1 = *(const float4*)(s_W + (k+1)*68 + c0);
            float4 w2 = *(const float4*)(s_W + (k+2)*68 + c0);
            float4 w3 = *(const float4*)(s_W + (k+3)*68 + c0);
            float4 x0 = *(const float4*)(Xp + k);
            float4 x1 = *(const float4*)(Xp + 68 + k);
            float4 x2 = *(const float4*)(Xp + 136 + k);
            float4 x3 = *(const float4*)(Xp + 204 + k);
            float4 x4 = *(const float4*)(Xp + 272 + k);
            a0.x += x0.x*w0.x + x0.y*w1.x + x0.z*w2.x + x0.w*w3.x;
            a0.y += x0.x*w0.y + x0.y*w1.y + x0.z*w2.y + x0.w*w3.y;
            a0.z += x0.x*w0.z + x0.y*w1.z + x0.z*w2.z + x0.w*w3.z;
            a0.w += x0.x*w0.w + x0.y*w1.w + x0.z*w2.w + x0.w*w3.w;
            a1.x += x1.x*w0.x + x1.y*w1.x + x1.z*w2.x + x1.w*w3.x;
            a1.y += x1.x*w0.y + x1.y*w1.y + x1.z*w2.y + x1.w*w3.y;
            a1.z += x1.x*w0.z + x1.y*w1.z + x1.z*w2.z + x1.w*w3.z;
            a1.w += x1.x*w0.w + x1.y*w1.w + x1.z*w2.w + x1.w*w3.w;
            a2.x += x2.x*w0.x + x2.y*w1.x + x2.z*w2.x + x2.w*w3.x;
            a2.y += x2.x*w0.y + x2.y*w1.y + x2.z*w2.y + x2.w*w3.y;
            a2.z += x2.x*w0.z + x2.y*w1.z + x2.z*w2.z + x2.w*w3.z;
            a2.w += x2.x*w0.w + x2.y*w1.w + x2.z*w2.w + x2.w*w3.w;
            a3.x += x3.x*w0.x + x3.y*w1.x + x3.z*w2.x + x3.w*w3.x;
            a3.y += x3.x*w0.y + x3.y*w1.y + x3.z*w2.y + x3.w*w3.y;
            a3.z += x3.x*w0.z + x3.y*w1.z + x3.z*w2.z + x3.w*w3.z;
            a3.w += x3.x*w0.w + x3.y*w1.w + x3.z*w2.w + x3.w*w3.w;
            a4.x += x4.x*w0.x + x4.y*w1.x + x4.z*w2.x + x4.w*w3.x;
            a4.y += x4.x*w0.y + x4.y*w1.y + x4.z*w2.y + x4.w*w3.y;
            a4.z += x4.x*w0.z + x4.y*w1.z + x4.z*w2.z + x4.w*w3.z;
            a4.w += x4.x*w0.w + x4.y*w1.w + x4.z*w2.w + x4.w*w3.w;
        }
        float4 acc[5] = {a0,a1,a2,a3,a4};
        #pragma unroll
        for (int i = 0; i < 5; i++){
            int r = r0 + i;
            if (r < 72){
                int n = base + r/9, m = r%9;
                float4 v = acc[i];
                if (m == 0){
                    v.x += s_b[c0]; v.y += s_b[c0+1]; v.z += s_b[c0+2]; v.w += s_b[c0+3];
                }
                *(float4*)(out + (size_t)n*576 + m*64 + c0) = v;
            }
        }
    }
}

extern "C" void kernel_launch(void* const* d_in, const int* in_sizes, int n_in,
                              void* d_out, int out_size)
{
    const float* node_input = (const float*)d_in[0];
    const float* edge_attr  = (const float*)d_in[1];
    const float* edge_scal  = (const float*)d_in[2];
    const float* W_src = (const float*)d_in[3];
    const float* b_src = (const float*)d_in[4];
    const float* W_dst = (const float*)d_in[5];
    const float* rW1   = (const float*)d_in[6];
    const float* rb1   = (const float*)d_in[7];
    const float* lng   = (const float*)d_in[8];
    const float* lnb   = (const float*)d_in[9];
    const float* rW2   = (const float*)d_in[10];
    const float* roff  = (const float*)d_in[11];
    const float* Wa    = (const float*)d_in[12];
    const float* ba    = (const float*)d_in[13];
    const float* adot  = (const float*)d_in[14];
    const float* Wv    = (const float*)d_in[15];
    const float* bv    = (const float*)d_in[16];
    const float* Wp    = (const float*)d_in[17];
    const float* bp    = (const float*)d_in[18];
    const int*   esrc  = (const int*)d_in[19];
    const int*   edst  = (const int*)d_in[20];
    float* out = (float*)d_out;

    const int smem_node = (64*128 + 40*68 + 64) * 4;
    const int smem_eA   = (64*68*2 + 192*68 + 512 + 16*68*4) * 4;   // ~106.5 KB
    const int smem_gate = (64*68 + 32*68 + 64) * 4;
    const int smem_eB   = (64*68 + 8*9*68 + 8*192 + 96 + 64 + 64) * 4;
    const int smem_out  = (64*68 + 80*68 + 64 + 64) * 4;

    cudaFuncSetAttribute(k_node,  cudaFuncAttributeMaxDynamicSharedMemorySize, smem_node);
    cudaFuncSetAttribute(k_edgeA, cudaFuncAttributeMaxDynamicSharedMemorySize, smem_eA);
    cudaFuncSetAttribute(k_gate,  cudaFuncAttributeMaxDynamicSharedMemorySize, smem_gate);
    cudaFuncSetAttribute(k_edgeB, cudaFuncAttributeMaxDynamicSharedMemorySize, smem_eB);
    cudaFuncSetAttribute(k_out,   cudaFuncAttributeMaxDynamicSharedMemorySize, smem_out);

    k_init<<<2048, 256>>>();
    k_node<<<296, 256, smem_node>>>(node_input, W_src, b_src, W_dst);
    k_edgeA<<<296, 256, smem_eA>>>(edge_scal, edge_attr, esrc, edst,
                                   rW1, rb1, lng, lnb, rW2, roff, Wa, ba, adot);
    k_gate<<<592, 256, smem_gate>>>(Wv, bv);
    k_edgeB<<<296, 256, smem_eB>>>(edge_attr, esrc, edst, Wv, bv);
    k_out<<<296, 256, smem_out>>>(Wp, bp, out);
}

// round 13
// speedup vs baseline: 1.1999x; 1.0160x over previous
#include <cuda_runtime.h>
#include <math.h>

#define NN 10000
#define NE 160000
#define MM 9
#define CC 64
#define HH 8

// ---------------- scratch (static device globals; no allocation) ----------------
__device__ float    g_xs[NN*MM*CC];        // node src-linear   (23 MB)
__device__ float    g_xd[NN*MM*CC];        // node dst-linear   (23 MB)
__device__ float    g_wlc[(size_t)NE*192]; // radial weights    (123 MB)
__device__ float    g_m0[(size_t)NE*64];   // msg row 0         (41 MB)
__device__ float    g_gate[(size_t)NE*64]; // sigmoid(gate)     (41 MB)
__device__ float    g_logit[NE*HH];
__device__ unsigned g_nmax[NN*HH];         // monotone-mapped float max
__device__ float    g_denom[NN*HH];
__device__ float    g_acc[NN*MM*CC];

__device__ __forceinline__ unsigned fkey(float f){
    int i = __float_as_int(f);
    return (i >= 0) ? ((unsigned)i ^ 0x80000000u) : ~(unsigned)i;
}
__device__ __forceinline__ float fdec(unsigned u){
    int i = (u & 0x80000000u) ? (int)(u ^ 0x80000000u) : (int)(~u);
    return __int_as_float(i);
}
__device__ __forceinline__ float sigf(float x){ return 1.f/(1.f + __expf(-x)); }

// packed fp32x2 FMA: d = a*b + d
__device__ __forceinline__ void ffma2(unsigned long long& d,
                                      unsigned long long a,
                                      unsigned long long b){
    asm("fma.rn.f32x2 %0, %1, %2, %0;" : "+l"(d) : "l"(a), "l"(b));
}
__device__ __forceinline__ float2 up2(unsigned long long v){
    float2 r; asm("mov.b64 {%0,%1}, %2;" : "=f"(r.x), "=f"(r.y) : "l"(v)); return r;
}

__global__ void k_init(){
    int i = blockIdx.x*blockDim.x + threadIdx.x;
    int st = gridDim.x*blockDim.x;
    for (int t = i; t < NN*MM*CC; t += st) g_acc[t] = 0.f;
    for (int t = i; t < NN*HH;    t += st){ g_denom[t] = 0.f; g_nmax[t] = fkey(-INFINITY); }
}

// ===== K1: node linear, FFMA2 (4 nodes -> X[40x64] @ W[64x128]) =================
// Weights stored transposed [col][k]; col (4t+i) at slot (t+32*i) so each
// lane's 4 column streams are conflict-free at 68-float stride.
__global__ __launch_bounds__(256) void k_node(
    const float* __restrict__ xin, const float* __restrict__ Ws,
    const float* __restrict__ bs,  const float* __restrict__ Wd)
{
    extern __shared__ float sm[];
    float* s_WT = sm;              // [128 slots][68]
    float* s_X  = s_WT + 128*68;   // [40][68]
    float* s_b  = s_X + 40*68;     // 64
    int tid = threadIdx.x;
    for (int t = tid; t < 8192; t += 256){
        int k = t>>7, c = t&127;
        float v = (c < 64) ? Ws[k*64 + c] : Wd[k*64 + (c-64)];
        int slot = (c&3)*32 + (c>>2);
        s_WT[slot*68 + k] = v;
    }
    if (tid < 64) s_b[tid] = bs[tid];
    for (int t = tid; t < 4*68; t += 256) s_X[36*68 + t] = 0.f;
    __syncthreads();

    int rg = tid>>5;              // warp id -> rows rg*5..rg*5+4
    int tx = tid&31;
    int c0 = tx*4;
    int r0 = rg*5;
    const float* Wp0 = s_WT + tx*68;
    const float* Wp1 = s_WT + (tx+32)*68;
    const float* Wp2 = s_WT + (tx+64)*68;
    const float* Wp3 = s_WT + (tx+96)*68;

    for (int base = blockIdx.x*4; base < NN; base += gridDim.x*4){
        __syncthreads();
        for (int i = tid; i < 576; i += 256){
            int n = i/144, rem = i - n*144;
            int row = n*9 + (rem>>4), c4 = (rem&15)*4;
            *(float4*)(s_X + row*68 + c4) =
                *(const float4*)(xin + (size_t)(base+n)*576 + (rem>>4)*64 + c4);
        }
        __syncthreads();
        unsigned long long q[5][4];
        #pragma unroll
        for (int r = 0; r < 5; r++)
            #pragma unroll
            for (int i = 0; i < 4; i++) q[r][i] = 0ull;
        const float* Xp = s_X + r0*68;
        #pragma unroll 4
        for (int k = 0; k < 64; k += 4){
            ulonglong2 w0 = *(const ulonglong2*)(Wp0 + k);
            ulonglong2 w1 = *(const ulonglong2*)(Wp1 + k);
            ulonglong2 w2 = *(const ulonglong2*)(Wp2 + k);
            ulonglong2 w3 = *(const ulonglong2*)(Wp3 + k);
            #pragma unroll
            for (int r = 0; r < 5; r++){
                ulonglong2 x = *(const ulonglong2*)(Xp + r*68 + k);
                ffma2(q[r][0], x.x, w0.x); ffma2(q[r][0], x.y, w0.y);
                ffma2(q[r][1], x.x, w1.x); ffma2(q[r][1], x.y, w1.y);
                ffma2(q[r][2], x.x, w2.x); ffma2(q[r][2], x.y, w2.y);
                ffma2(q[r][3], x.x, w3.x); ffma2(q[r][3], x.y, w3.y);
            }
        }
        #pragma unroll
        for (int i = 0; i < 5; i++){
            int r = r0 + i;
            if (r < 36){
                int n = base + r/9, m = r%9;
                float2 p0 = up2(q[i][0]), p1 = up2(q[i][1]);
                float2 p2 = up2(q[i][2]), p3 = up2(q[i][3]);
                float4 v;
                v.x = p0.x+p0.y; v.y = p1.x+p1.y; v.z = p2.x+p2.y; v.w = p3.x+p3.y;
                if (m == 0 && c0 < 64){
                    v.x += s_b[c0]; v.y += s_b[c0+1]; v.z += s_b[c0+2]; v.w += s_b[c0+3];
                }
                if (c0 < 64) *(float4*)(g_xs + (size_t)n*576 + m*64 + c0) = v;
                else         *(float4*)(g_xd + (size_t)n*576 + m*64 + (c0-64)) = v;
            }
        }
    }
}

// ===== K2: radial MLP + alpha logits, FFMA2 (16 edges/iter, 256t) ===============
__global__ __launch_bounds__(256) void k_edgeA(
    const float* __restrict__ esc, const float* __restrict__ eattr,
    const int* __restrict__ esrc,  const int* __restrict__ edst,
    const float* __restrict__ W1,  const float* __restrict__ b1,
    const float* __restrict__ lng, const float* __restrict__ lnb,
    const float* __restrict__ W2,  const float* __restrict__ off,
    const float* __restrict__ Wa,  const float* __restrict__ ba,
    const float* __restrict__ adot)
{
    extern __shared__ float sm[];
    float* s_W1T = sm;                // [64 slots][68]
    float* s_WaT = s_W1T + 64*68;     // [64 slots][68]
    float* s_W2T = s_WaT + 64*68;     // [192 cols][68]
    float* cb    = s_W2T + 192*68;    // b1|lng|lnb|ba|adot|off = 512
    float* s_S   = cb + 512;          // [16][68]
    float* s_H   = s_S + 16*68;       // [16][68]
    float* s_M0  = s_H + 16*68;       // [16][68]
    float* s_wl0 = s_M0 + 16*68;      // [16][68]
    int tid = threadIdx.x;
    for (int t = tid; t < 4096; t += 256){
        int k = t>>6, j = t&63;
        int slot = (j&3)*16 + (j>>2);
        s_W1T[slot*68 + k] = W1[t];
        s_WaT[slot*68 + k] = Wa[t];
    }
    for (int t = tid; t < 12288; t += 256){
        int k = t/192, c = t - k*192;
        s_W2T[c*68 + k] = W2[t];
    }
    if (tid < 64){
        cb[tid] = b1[tid]; cb[64+tid] = lng[tid]; cb[128+tid] = lnb[tid];
        cb[192+tid] = ba[tid]; cb[256+tid] = adot[tid];
    }
    for (int t = tid; t < 192; t += 256) cb[320+t] = off[t];
    __syncthreads();

    int rg = tid>>4;            // 0..15 (edge row)
    int tx = tid&15;
    int c0 = tx*4;
    const float* W1p0 = s_W1T + tx*68;
    const float* W1p1 = s_W1T + (tx+16)*68;
    const float* W1p2 = s_W1T + (tx+32)*68;
    const float* W1p3 = s_W1T + (tx+48)*68;
    const float* Wap0 = s_WaT + tx*68;
    const float* Wap1 = s_WaT + (tx+16)*68;
    const float* Wap2 = s_WaT + (tx+32)*68;
    const float* Wap3 = s_WaT + (tx+48)*68;

    for (int base = blockIdx.x*16; base < NE; base += gridDim.x*16){
        __syncthreads();
        for (int i = tid; i < 16*16; i += 256){       // float4 staging of scalars
            int e = i>>4, c4 = (i&15)*4;
            *(float4*)(s_S + e*68 + c4) = *(const float4*)(esc + (size_t)(base+e)*64 + c4);
        }
        __syncthreads();
        // GEMM1: H = S @ W1  (FFMA2)
        {
            unsigned long long q0=0ull,q1=0ull,q2=0ull,q3=0ull;
            const float* Xp = s_S + rg*68;
            #pragma unroll 4
            for (int k = 0; k < 64; k += 4){
                ulonglong2 x  = *(const ulonglong2*)(Xp + k);
                ulonglong2 w0 = *(const ulonglong2*)(W1p0 + k);
                ulonglong2 w1 = *(const ulonglong2*)(W1p1 + k);
                ulonglong2 w2 = *(const ulonglong2*)(W1p2 + k);
                ulonglong2 w3 = *(const ulonglong2*)(W1p3 + k);
                ffma2(q0, x.x, w0.x); ffma2(q0, x.y, w0.y);
                ffma2(q1, x.x, w1.x); ffma2(q1, x.y, w1.y);
                ffma2(q2, x.x, w2.x); ffma2(q2, x.y, w2.y);
                ffma2(q3, x.x, w3.x); ffma2(q3, x.y, w3.y);
            }
            float2 p0=up2(q0), p1=up2(q1), p2=up2(q2), p3=up2(q3);
            float4 a;
            a.x = p0.x+p0.y + cb[c0  ];
            a.y = p1.x+p1.y + cb[c0+1];
            a.z = p2.x+p2.y + cb[c0+2];
            a.w = p3.x+p3.y + cb[c0+3];
            float s = a.x+a.y+a.z+a.w;
            float q = a.x*a.x+a.y*a.y+a.z*a.z+a.w*a.w;
            #pragma unroll
            for (int o = 8; o > 0; o >>= 1){
                s += __shfl_xor_sync(0xffffffffu, s, o);
                q += __shfl_xor_sync(0xffffffffu, q, o);
            }
            float mu = s*(1.f/64.f);
            float var = q*(1.f/64.f) - mu*mu;
            float rs = rsqrtf(var + 1e-5f);
            float4 h;
            h.x = (a.x-mu)*rs*cb[64+c0  ] + cb[128+c0  ];
            h.y = (a.y-mu)*rs*cb[64+c0+1] + cb[128+c0+1];
            h.z = (a.z-mu)*rs*cb[64+c0+2] + cb[128+c0+2];
            h.w = (a.w-mu)*rs*cb[64+c0+3] + cb[128+c0+3];
            h.x *= sigf(h.x); h.y *= sigf(h.y); h.z *= sigf(h.z); h.w *= sigf(h.w);
            *(float4*)(s_H + rg*68 + c0) = h;
        }
        __syncthreads();
        // GEMM2: WL = H @ W2  (FFMA2, write g_wlc directly, stash wl0)
        {
            int rgr = tid>>6;
            int cc  = tid&63;
            unsigned long long acc[4][3];
            #pragma unroll
            for (int i = 0; i < 4; i++){ acc[i][0]=0ull; acc[i][1]=0ull; acc[i][2]=0ull; }
            const float* Wp0 = s_W2T + cc*68;
            const float* Wp1 = s_W2T + (cc+64)*68;
            const float* Wp2 = s_W2T + (cc+128)*68;
            #pragma unroll 4
            for (int k = 0; k < 64; k += 4){
                ulonglong2 w0 = *(const ulonglong2*)(Wp0 + k);
                ulonglong2 w1 = *(const ulonglong2*)(Wp1 + k);
                ulonglong2 w2 = *(const ulonglong2*)(Wp2 + k);
                ulonglong2 x0 = *(const ulonglong2*)(s_H + (rgr   )*68 + k);
                ulonglong2 x1 = *(const ulonglong2*)(s_H + (rgr+4 )*68 + k);
                ulonglong2 x2 = *(const ulonglong2*)(s_H + (rgr+8 )*68 + k);
                ulonglong2 x3 = *(const ulonglong2*)(s_H + (rgr+12)*68 + k);
                ffma2(acc[0][0], x0.x, w0.x); ffma2(acc[0][0], x0.y, w0.y);
                ffma2(acc[0][1], x0.x, w1.x); ffma2(acc[0][1], x0.y, w1.y);
                ffma2(acc[0][2], x0.x, w2.x); ffma2(acc[0][2], x0.y, w2.y);
                ffma2(acc[1][0], x1.x, w0.x); ffma2(acc[1][0], x1.y, w0.y);
                ffma2(acc[1][1], x1.x, w1.x); ffma2(acc[1][1], x1.y, w1.y);
                ffma2(acc[1][2], x1.x, w2.x); ffma2(acc[1][2], x1.y, w2.y);
                ffma2(acc[2][0], x2.x, w0.x); ffma2(acc[2][0], x2.y, w0.y);
                ffma2(acc[2][1], x2.x, w1.x); ffma2(acc[2][1], x2.y, w1.y);
                ffma2(acc[2][2], x2.x, w2.x); ffma2(acc[2][2], x2.y, w2.y);
                ffma2(acc[3][0], x3.x, w0.x); ffma2(acc[3][0], x3.y, w0.y);
                ffma2(acc[3][1], x3.x, w1.x); ffma2(acc[3][1], x3.y, w1.y);
                ffma2(acc[3][2], x3.x, w2.x); ffma2(acc[3][2], x3.y, w2.y);
            }
            #pragma unroll
            for (int i = 0; i < 4; i++){
                int r = rgr + i*4;
                #pragma unroll
                for (int j = 0; j < 3; j++){
                    float2 p = up2(acc[i][j]);
                    float v = p.x + p.y + cb[320 + cc + 64*j];
                    g_wlc[(size_t)(base+r)*192 + cc + 64*j] = v;
                    if (j == 0) s_wl0[r*68 + cc] = v;
                }
            }
        }
        __syncthreads();
        // M0 build (+ park to gmem for k_gate)
        int dst;
        {
            int e = rg;
            int src = esrc[base+e]; dst = edst[base+e];
            float ea0 = eattr[(size_t)(base+e)*9];
            float4 xs = *(const float4*)(g_xs + (size_t)src*576 + c0);
            float4 xd = *(const float4*)(g_xd + (size_t)dst*576 + c0);
            float4 wl = *(const float4*)(s_wl0 + e*68 + c0);
            float4 m0;
            m0.x = (xs.x+xd.x)*ea0*wl.x; m0.y = (xs.y+xd.y)*ea0*wl.y;
            m0.z = (xs.z+xd.z)*ea0*wl.z; m0.w = (xs.w+xd.w)*ea0*wl.w;
            *(float4*)(s_M0 + e*68 + c0) = m0;
            *(float4*)(g_m0 + (size_t)(base+e)*64 + c0) = m0;
        }
        __syncthreads();
        // GEMM3: alpha logits (FFMA2)
        {
            unsigned long long q0=0ull,q1=0ull,q2=0ull,q3=0ull;
            const float* Xp = s_M0 + rg*68;
            #pragma unroll 4
            for (int k = 0; k < 64; k += 4){
                ulonglong2 x  = *(const ulonglong2*)(Xp + k);
                ulonglong2 w0 = *(const ulonglong2*)(Wap0 + k);
                ulonglong2 w1 = *(const ulonglong2*)(Wap1 + k);
                ulonglong2 w2 = *(const ulonglong2*)(Wap2 + k);
                ulonglong2 w3 = *(const ulonglong2*)(Wap3 + k);
                ffma2(q0, x.x, w0.x); ffma2(q0, x.y, w0.y);
                ffma2(q1, x.x, w1.x); ffma2(q1, x.y, w1.y);
                ffma2(q2, x.x, w2.x); ffma2(q2, x.y, w2.y);
                ffma2(q3, x.x, w3.x); ffma2(q3, x.y, w3.y);
            }
            float2 p0=up2(q0), p1=up2(q1), p2=up2(q2), p3=up2(q3);
            float4 a;
            a.x = p0.x+p0.y + cb[192+c0  ];
            a.y = p1.x+p1.y + cb[192+c0+1];
            a.z = p2.x+p2.y + cb[192+c0+2];
            a.w = p3.x+p3.y + cb[192+c0+3];
            a.x = 0.2f*a.x + 0.8f*a.x*sigf(a.x);
            a.y = 0.2f*a.y + 0.8f*a.y*sigf(a.y);
            a.z = 0.2f*a.z + 0.8f*a.z*sigf(a.z);
            a.w = 0.2f*a.w + 0.8f*a.w*sigf(a.w);
            float s4 = a.x*cb[256+c0] + a.y*cb[256+c0+1] + a.z*cb[256+c0+2] + a.w*cb[256+c0+3];
            float lg = s4 + __shfl_xor_sync(0xffffffffu, s4, 1);
            if ((tx & 1) == 0){
                int h = tx >> 1;
                g_logit[(size_t)(base+rg)*8 + h] = lg;
                atomicMax(&g_nmax[dst*8 + h], fkey(lg));
            }
        }
    }
}

// ================= K2b: gate = sigmoid(M0 @ Wg + bg) — dense FFMA2 GEMM ========
__global__ __launch_bounds__(256) void k_gate(
    const float* __restrict__ Wv, const float* __restrict__ bv)
{
    extern __shared__ float sm[];
    float* s_Wt = sm;             // [64][68] transposed gate cols
    float* s_X  = s_Wt + 64*68;   // [32][68]
    float* s_b  = s_X + 32*68;    // 64
    int tid = threadIdx.x;
    for (int t = tid; t < 4096; t += 256){
        int k = t>>6, c = t&63;
        s_Wt[c*68 + k] = Wv[k*128 + 64 + c];
    }
    if (tid < 64) s_b[tid] = bv[64 + tid];
    __syncthreads();

    int rgr = tid>>6;     // 0..3
    int cc  = tid&63;
    const float* Wc = s_Wt + cc*68;

    for (int base = blockIdx.x*32; base < NE; base += gridDim.x*32){
        __syncthreads();
        for (int i = tid; i < 512; i += 256){            // float4 staging
            int e = i>>4, c4 = (i&15)*4;
            *(float4*)(s_X + e*68 + c4) = *(const float4*)(g_m0 + (size_t)(base+e)*64 + c4);
        }
        __syncthreads();
        unsigned long long acc[8];
        #pragma unroll
        for (int i = 0; i < 8; i++) acc[i] = 0ull;
        #pragma unroll 4
        for (int k = 0; k < 64; k += 4){
            ulonglong2 w = *(const ulonglong2*)(Wc + k);
            #pragma unroll
            for (int i = 0; i < 8; i++){
                ulonglong2 x = *(const ulonglong2*)(s_X + (rgr + 4*i)*68 + k);
                ffma2(acc[i], x.x, w.x);
                ffma2(acc[i], x.y, w.y);
            }
        }
        float bb = s_b[cc];
        #pragma unroll
        for (int i = 0; i < 8; i++){
            float2 p = up2(acc[i]);
            g_gate[(size_t)(base + rgr + 4*i)*64 + cc] = sigf(p.x + p.y + bb);
        }
    }
}

// ================= K3: value GEMM + weighted scatter, FFMA2, warp-per-edge ======
__global__ __launch_bounds__(256, 2) void k_edgeB(
    const float* __restrict__ eattr, const int* __restrict__ esrc,
    const int* __restrict__ edst,    const float* __restrict__ Wv,
    const float* __restrict__ bv)
{
    extern __shared__ float sm[];
    float* s_Wt = sm;                 // [64][68] transposed value cols
    float* s_X  = s_Wt + 64*68;       // [8 warps][9 rows][68]
    float* s_wl = s_X + 8*9*68;       // [8][192]
    float* s_ea = s_wl + 8*192;       // [8][12]
    float* s_sw = s_ea + 96;          // [8][8]
    float* s_bv = s_sw + 64;          // 64
    int tid = threadIdx.x;
    for (int t = tid; t < 4096; t += 256){
        int k = t>>6, c = t&63;
        s_Wt[c*68 + k] = Wv[k*128 + c];
    }
    if (tid < 64) s_bv[tid] = bv[tid];
    __syncthreads();

    int w = tid>>5, lane = tid&31;
    float* myX  = s_X  + w*9*68;
    float* mywl = s_wl + w*192;
    float* myea = s_ea + w*12;
    float* mysw = s_sw + w*8;
    const float* Wc0 = s_Wt + lane*68;
    const float* Wc1 = s_Wt + (lane+32)*68;
    int gw = blockIdx.x*8 + w;

    for (int e = gw; e < NE; e += 2368){
        int src = esrc[e], dst = edst[e];
        float gate0 = g_gate[(size_t)e*64 + lane];
        float gate1 = g_gate[(size_t)e*64 + lane + 32];
        #pragma unroll
        for (int t = lane; t < 48; t += 32){
            float4 v = *(const float4*)(g_wlc + (size_t)e*192 + t*4);
            *(float4*)(mywl + t*4) = v;
        }
        if (lane < 9) myea[lane] = eattr[(size_t)e*9 + lane];
        if (lane < 8){
            float lg = g_logit[(size_t)e*8 + lane];
            float mx = fdec(g_nmax[dst*8 + lane]);
            float ww = __expf(lg - mx);
            mysw[lane] = ww;
            atomicAdd(&g_denom[dst*8 + lane], ww);
        }
        __syncwarp();
        #pragma unroll
        for (int m = 0; m < 9; m++){
            int lsel = (m==0) ? 0 : (m<4) ? 1 : 2;
            float2 a = *(const float2*)(g_xs + (size_t)src*576 + m*64 + 2*lane);
            float2 b = *(const float2*)(g_xd + (size_t)dst*576 + m*64 + 2*lane);
            float eam = myea[m];
            float2 wl2 = *(const float2*)(mywl + lsel*64 + 2*lane);
            float2 v; v.x = (a.x+b.x)*eam*wl2.x; v.y = (a.y+b.y)*eam*wl2.y;
            *(float2*)(myX + m*68 + 2*lane) = v;
        }
        __syncwarp();
        unsigned long long accv[9][2];
        #pragma unroll
        for (int m = 0; m < 9; m++){ accv[m][0] = 0ull; accv[m][1] = 0ull; }
        #pragma unroll 4
        for (int k = 0; k < 64; k += 4){
            ulonglong2 w0 = *(const ulonglong2*)(Wc0 + k);
            ulonglong2 w1 = *(const ulonglong2*)(Wc1 + k);
            #pragma unroll
            for (int m = 0; m < 9; m++){
                ulonglong2 x = *(const ulonglong2*)(myX + m*68 + k);
                ffma2(accv[m][0], x.x, w0.x); ffma2(accv[m][0], x.y, w0.y);
                ffma2(accv[m][1], x.x, w1.x); ffma2(accv[m][1], x.y, w1.y);
            }
        }
        __syncwarp();
        {
            float whA = mysw[lane>>3];
            float whB = mysw[(lane+32)>>3];
            #pragma unroll
            for (int m = 0; m < 9; m++){
                int lsel = (m==0) ? 0 : (m<4) ? 1 : 2;
                float2 vA = up2(accv[m][0]);
                float2 vB = up2(accv[m][1]);
                float yA = vA.x + vA.y;
                float yB = vB.x + vB.y;
                float oA, oB;
                if (m == 0){
                    yA += s_bv[lane]; yB += s_bv[lane+32];
                    oA = yA * sigf(yA); oB = yB * sigf(yB);
                } else {
                    oA = yA * gate0; oB = yB * gate1;
                }
                float eam = myea[m];
                oA *= eam * mywl[lsel*64 + lane]      * whA;
                oB *= eam * mywl[lsel*64 + lane + 32] * whB;
                myX[m*68 + lane]      = oA;
                myX[m*68 + lane + 32] = oB;
            }
        }
        __syncwarp();
        float* accp = g_acc + (size_t)dst*576;
        #pragma unroll
        for (int t = lane; t < 144; t += 32){
            int r = t>>4, c4 = (t&15)*4;
            float4 v = *(const float4*)(myX + r*68 + c4);
            atomicAdd((float4*)(accp + r*64 + c4), v);
        }
        __syncwarp();
    }
}

// ===== K4: normalize + projection, FFMA2 (8 nodes/iter) =========================
__global__ __launch_bounds__(256) void k_out(
    const float* __restrict__ Wp, const float* __restrict__ bp, float* __restrict__ out)
{
    extern __shared__ float sm[];
    float* s_WT = sm;              // [64 slots][68]
    float* s_X  = s_WT + 64*68;    // [80][68]
    float* s_b  = s_X + 80*68;     // 64
    float* s_inv= s_b + 64;        // 64
    int tid = threadIdx.x;
    for (int t = tid; t < 4096; t += 256){
        int k = t>>6, j = t&63;
        int slot = (j&3)*16 + (j>>2);
        s_WT[slot*68 + k] = Wp[t];
    }
    if (tid < 64) s_b[tid] = bp[tid];
    for (int t = tid; t < 8*68; t += 256) s_X[72*68 + t] = 0.f;
    __syncthreads();

    int rg = tid>>4, tx = tid&15, c0 = tx*4, r0 = rg*5;
    const float* Wp0 = s_WT + tx*68;
    const float* Wp1 = s_WT + (tx+16)*68;
    const float* Wp2 = s_WT + (tx+32)*68;
    const float* Wp3 = s_WT + (tx+48)*68;

    for (int base = blockIdx.x*8; base < NN; base += gridDim.x*8){
        __syncthreads();
        if (tid < 64){
            int e = tid>>3, h = tid&7;
            s_inv[tid] = 1.f/(g_denom[(base+e)*8 + h] + 1e-16f);
        }
        __syncthreads();
        for (int i = tid; i < 1152; i += 256){
            int n = i/144, rem = i - n*144;
            int row = n*9 + (rem>>4), c4 = (rem&15)*4;
            float inv = s_inv[n*8 + (c4>>3)];
            float4 v = *(const float4*)(g_acc + (size_t)(base+n)*576 + (rem>>4)*64 + c4);
            v.x *= inv; v.y *= inv; v.z *= inv; v.w *= inv;
            *(float4*)(s_X + row*68 + c4) = v;
        }
        __syncthreads();
        unsigned long long q[5][4];
        #pragma unroll
        for (int r = 0; r < 5; r++)
            #pragma unroll
            for (int i = 0; i < 4; i++) q[r][i] = 0ull;
        const float* Xp = s_X + r0*68;
        #pragma unroll 4
        for (int k = 0; k < 64; k += 4){
            ulonglong2 w0 = *(const ulonglong2*)(Wp0 + k);
            ulonglong2 w1 = *(const ulonglong2*)(Wp1 + k);
            ulonglong2 w2 = *(const ulonglong2*)(Wp2 + k);
            ulonglong2 w3 = *(const ulonglong2*)(Wp3 + k);
            #pragma unroll
            for (int r = 0; r < 5; r++){
                ulonglong2 x = *(const ulonglong2*)(Xp + r*68 + k);
                ffma2(q[r][0], x.x, w0.x); ffma2(q[r][0], x.y, w0.y);
                ffma2(q[r][1], x.x, w1.x); ffma2(q[r][1], x.y, w1.y);
                ffma2(q[r][2], x.x, w2.x); ffma2(q[r][2], x.y, w2.y);
                ffma2(q[r][3], x.x, w3.x); ffma2(q[r][3], x.y, w3.y);
            }
        }
        #pragma unroll
        for (int i = 0; i < 5; i++){
            int r = r0 + i;
            if (r < 72){
                int n = base + r/9, m = r%9;
                float2 p0 = up2(q[i][0]), p1 = up2(q[i][1]);
                float2 p2 = up2(q[i][2]), p3 = up2(q[i][3]);
                float4 v;
                v.x = p0.x+p0.y; v.y = p1.x+p1.y; v.z = p2.x+p2.y; v.w = p3.x+p3.y;
                if (m == 0){
                    v.x += s_b[c0]; v.y += s_b[c0+1]; v.z += s_b[c0+2]; v.w += s_b[c0+3];
                }
                *(float4*)(out + (size_t)n*576 + m*64 + c0) = v;
            }
        }
    }
}

extern "C" void kernel_launch(void* const* d_in, const int* in_sizes, int n_in,
                              void* d_out, int out_size)
{
    const float* node_input = (const float*)d_in[0];
    const float* edge_attr  = (const float*)d_in[1];
    const float* edge_scal  = (const float*)d_in[2];
    const float* W_src = (const float*)d_in[3];
    const float* b_src = (const float*)d_in[4];
    const float* W_dst = (const float*)d_in[5];
    const float* rW1   = (const float*)d_in[6];
    const float* rb1   = (const float*)d_in[7];
    const float* lng   = (const float*)d_in[8];
    const float* lnb   = (const float*)d_in[9];
    const float* rW2   = (const float*)d_in[10];
    const float* roff  = (const float*)d_in[11];
    const float* Wa    = (const float*)d_in[12];
    const float* ba    = (const float*)d_in[13];
    const float* adot  = (const float*)d_in[14];
    const float* Wv    = (const float*)d_in[15];
    const float* bv    = (const float*)d_in[16];
    const float* Wp    = (const float*)d_in[17];
    const float* bp    = (const float*)d_in[18];
    const int*   esrc  = (const int*)d_in[19];
    const int*   edst  = (const int*)d_in[20];
    float* out = (float*)d_out;

    const int smem_node = (128*68 + 40*68 + 64) * 4;
    const int smem_eA   = (64*68*2 + 192*68 + 512 + 16*68*4) * 4;   // ~106.5 KB
    const int smem_gate = (64*68 + 32*68 + 64) * 4;
    const int smem_eB   = (64*68 + 8*9*68 + 8*192 + 96 + 64 + 64) * 4;
    const int smem_out  = (64*68 + 80*68 + 64 + 64) * 4;

    cudaFuncSetAttribute(k_node,  cudaFuncAttributeMaxDynamicSharedMemorySize, smem_node);
    cudaFuncSetAttribute(k_edgeA, cudaFuncAttributeMaxDynamicSharedMemorySize, smem_eA);
    cudaFuncSetAttribute(k_gate,  cudaFuncAttributeMaxDynamicSharedMemorySize, smem_gate);
    cudaFuncSetAttribute(k_edgeB, cudaFuncAttributeMaxDynamicSharedMemorySize, smem_eB);
    cudaFuncSetAttribute(k_out,   cudaFuncAttributeMaxDynamicSharedMemorySize, smem_out);

    k_init<<<2048, 256>>>();
    k_node<<<296, 256, smem_node>>>(node_input, W_src, b_src, W_dst);
    k_edgeA<<<296, 256, smem_eA>>>(edge_scal, edge_attr, esrc, edst,
                                   rW1, rb1, lng, lnb, rW2, roff, Wa, ba, adot);
    k_gate<<<592, 256, smem_gate>>>(Wv, bv);
    k_edgeB<<<296, 256, smem_eB>>>(edge_attr, esrc, edst, Wv, bv);
    k_out<<<296, 256, smem_out>>>(Wp, bp, out);
}

// round 14
// speedup vs baseline: 1.2155x; 1.0130x over previous
#include <cuda_runtime.h>
#include <math.h>

#define NN 10000
#define NE 160000
#define MM 9
#define CC 64
#define HH 8

// ---------------- scratch (static device globals; no allocation) ----------------
__device__ float    g_xs[NN*MM*CC];        // node src-linear   (23 MB)
__device__ float    g_xd[NN*MM*CC];        // node dst-linear   (23 MB)
__device__ float    g_wlc[(size_t)NE*192]; // radial weights    (123 MB)
__device__ float    g_m0[(size_t)NE*64];   // msg row 0         (41 MB)
__device__ float    g_gate[(size_t)NE*64]; // sigmoid(gate)     (41 MB)
__device__ float    g_logit[NE*HH];        // exp(logit) (unnormalized softmax w)
__device__ float    g_denom[NN*HH];
__device__ float    g_acc[NN*MM*CC];

__device__ __forceinline__ float sigf(float x){ return 1.f/(1.f + __expf(-x)); }

// packed fp32x2 FMA: d = a*b + d
__device__ __forceinline__ void ffma2(unsigned long long& d,
                                      unsigned long long a,
                                      unsigned long long b){
    asm("fma.rn.f32x2 %0, %1, %2, %0;" : "+l"(d) : "l"(a), "l"(b));
}
__device__ __forceinline__ float2 up2(unsigned long long v){
    float2 r; asm("mov.b64 {%0,%1}, %2;" : "=f"(r.x), "=f"(r.y) : "l"(v)); return r;
}

__global__ void k_init(){
    int i = blockIdx.x*blockDim.x + threadIdx.x;
    int st = gridDim.x*blockDim.x;
    for (int t = i; t < NN*MM*CC; t += st) g_acc[t] = 0.f;
    for (int t = i; t < NN*HH;    t += st) g_denom[t] = 0.f;
}

// ===== K1: node linear, FFMA2 (4 nodes -> X[40x64] @ W[64x128]) =================
__global__ __launch_bounds__(256) void k_node(
    const float* __restrict__ xin, const float* __restrict__ Ws,
    const float* __restrict__ bs,  const float* __restrict__ Wd)
{
    extern __shared__ float sm[];
    float* s_WT = sm;              // [128 slots][68]
    float* s_X  = s_WT + 128*68;   // [40][68]
    float* s_b  = s_X + 40*68;     // 64
    int tid = threadIdx.x;
    for (int t = tid; t < 8192; t += 256){
        int k = t>>7, c = t&127;
        float v = (c < 64) ? Ws[k*64 + c] : Wd[k*64 + (c-64)];
        int slot = (c&3)*32 + (c>>2);
        s_WT[slot*68 + k] = v;
    }
    if (tid < 64) s_b[tid] = bs[tid];
    for (int t = tid; t < 4*68; t += 256) s_X[36*68 + t] = 0.f;
    __syncthreads();

    int rg = tid>>5;
    int tx = tid&31;
    int c0 = tx*4;
    int r0 = rg*5;
    const float* Wp0 = s_WT + tx*68;
    const float* Wp1 = s_WT + (tx+32)*68;
    const float* Wp2 = s_WT + (tx+64)*68;
    const float* Wp3 = s_WT + (tx+96)*68;

    for (int base = blockIdx.x*4; base < NN; base += gridDim.x*4){
        __syncthreads();
        for (int i = tid; i < 576; i += 256){
            int n = i/144, rem = i - n*144;
            int row = n*9 + (rem>>4), c4 = (rem&15)*4;
            *(float4*)(s_X + row*68 + c4) =
                *(const float4*)(xin + (size_t)(base+n)*576 + (rem>>4)*64 + c4);
        }
        __syncthreads();
        unsigned long long q[5][4];
        #pragma unroll
        for (int r = 0; r < 5; r++)
            #pragma unroll
            for (int i = 0; i < 4; i++) q[r][i] = 0ull;
        const float* Xp = s_X + r0*68;
        #pragma unroll 4
        for (int k = 0; k < 64; k += 4){
            ulonglong2 w0 = *(const ulonglong2*)(Wp0 + k);
            ulonglong2 w1 = *(const ulonglong2*)(Wp1 + k);
            ulonglong2 w2 = *(const ulonglong2*)(Wp2 + k);
            ulonglong2 w3 = *(const ulonglong2*)(Wp3 + k);
            #pragma unroll
            for (int r = 0; r < 5; r++){
                ulonglong2 x = *(const ulonglong2*)(Xp + r*68 + k);
                ffma2(q[r][0], x.x, w0.x); ffma2(q[r][0], x.y, w0.y);
                ffma2(q[r][1], x.x, w1.x); ffma2(q[r][1], x.y, w1.y);
                ffma2(q[r][2], x.x, w2.x); ffma2(q[r][2], x.y, w2.y);
                ffma2(q[r][3], x.x, w3.x); ffma2(q[r][3], x.y, w3.y);
            }
        }
        #pragma unroll
        for (int i = 0; i < 5; i++){
            int r = r0 + i;
            if (r < 36){
                int n = base + r/9, m = r%9;
                float2 p0 = up2(q[i][0]), p1 = up2(q[i][1]);
                float2 p2 = up2(q[i][2]), p3 = up2(q[i][3]);
                float4 v;
                v.x = p0.x+p0.y; v.y = p1.x+p1.y; v.z = p2.x+p2.y; v.w = p3.x+p3.y;
                if (m == 0 && c0 < 64){
                    v.x += s_b[c0]; v.y += s_b[c0+1]; v.z += s_b[c0+2]; v.w += s_b[c0+3];
                }
                if (c0 < 64) *(float4*)(g_xs + (size_t)n*576 + m*64 + c0) = v;
                else         *(float4*)(g_xd + (size_t)n*576 + m*64 + (c0-64)) = v;
            }
        }
    }
}

// ===== K2: radial MLP + softmax weights, FFMA2 (16 edges/iter, 256t) ============
__global__ __launch_bounds__(256) void k_edgeA(
    const float* __restrict__ esc, const float* __restrict__ eattr,
    const int* __restrict__ esrc,  const int* __restrict__ edst,
    const float* __restrict__ W1,  const float* __restrict__ b1,
    const float* __restrict__ lng, const float* __restrict__ lnb,
    const float* __restrict__ W2,  const float* __restrict__ off,
    const float* __restrict__ Wa,  const float* __restrict__ ba,
    const float* __restrict__ adot)
{
    extern __shared__ float sm[];
    float* s_W1T = sm;                // [64 slots][68]
    float* s_WaT = s_W1T + 64*68;     // [64 slots][68]
    float* s_W2T = s_WaT + 64*68;     // [192 cols][68]
    float* cb    = s_W2T + 192*68;    // b1|lng|lnb|ba|adot|off = 512
    float* s_S   = cb + 512;          // [16][68]
    float* s_H   = s_S + 16*68;       // [16][68]
    float* s_M0  = s_H + 16*68;       // [16][68]
    float* s_wl0 = s_M0 + 16*68;      // [16][68]
    int tid = threadIdx.x;
    for (int t = tid; t < 4096; t += 256){
        int k = t>>6, j = t&63;
        int slot = (j&3)*16 + (j>>2);
        s_W1T[slot*68 + k] = W1[t];
        s_WaT[slot*68 + k] = Wa[t];
    }
    for (int t = tid; t < 12288; t += 256){
        int k = t/192, c = t - k*192;
        s_W2T[c*68 + k] = W2[t];
    }
    if (tid < 64){
        cb[tid] = b1[tid]; cb[64+tid] = lng[tid]; cb[128+tid] = lnb[tid];
        cb[192+tid] = ba[tid]; cb[256+tid] = adot[tid];
    }
    for (int t = tid; t < 192; t += 256) cb[320+t] = off[t];
    __syncthreads();

    int rg = tid>>4;            // 0..15 (edge row)
    int tx = tid&15;
    int c0 = tx*4;
    const float* W1p0 = s_W1T + tx*68;
    const float* W1p1 = s_W1T + (tx+16)*68;
    const float* W1p2 = s_W1T + (tx+32)*68;
    const float* W1p3 = s_W1T + (tx+48)*68;
    const float* Wap0 = s_WaT + tx*68;
    const float* Wap1 = s_WaT + (tx+16)*68;
    const float* Wap2 = s_WaT + (tx+32)*68;
    const float* Wap3 = s_WaT + (tx+48)*68;

    for (int base = blockIdx.x*16; base < NE; base += gridDim.x*16){
        __syncthreads();
        for (int i = tid; i < 16*16; i += 256){
            int e = i>>4, c4 = (i&15)*4;
            *(float4*)(s_S + e*68 + c4) = *(const float4*)(esc + (size_t)(base+e)*64 + c4);
        }
        __syncthreads();
        // GEMM1: H = S @ W1  (FFMA2)
        {
            unsigned long long q0=0ull,q1=0ull,q2=0ull,q3=0ull;
            const float* Xp = s_S + rg*68;
            #pragma unroll 4
            for (int k = 0; k < 64; k += 4){
                ulonglong2 x  = *(const ulonglong2*)(Xp + k);
                ulonglong2 w0 = *(const ulonglong2*)(W1p0 + k);
                ulonglong2 w1 = *(const ulonglong2*)(W1p1 + k);
                ulonglong2 w2 = *(const ulonglong2*)(W1p2 + k);
                ulonglong2 w3 = *(const ulonglong2*)(W1p3 + k);
                ffma2(q0, x.x, w0.x); ffma2(q0, x.y, w0.y);
                ffma2(q1, x.x, w1.x); ffma2(q1, x.y, w1.y);
                ffma2(q2, x.x, w2.x); ffma2(q2, x.y, w2.y);
                ffma2(q3, x.x, w3.x); ffma2(q3, x.y, w3.y);
            }
            float2 p0=up2(q0), p1=up2(q1), p2=up2(q2), p3=up2(q3);
            float4 a;
            a.x = p0.x+p0.y + cb[c0  ];
            a.y = p1.x+p1.y + cb[c0+1];
            a.z = p2.x+p2.y + cb[c0+2];
            a.w = p3.x+p3.y + cb[c0+3];
            float s = a.x+a.y+a.z+a.w;
            float q = a.x*a.x+a.y*a.y+a.z*a.z+a.w*a.w;
            #pragma unroll
            for (int o = 8; o > 0; o >>= 1){
                s += __shfl_xor_sync(0xffffffffu, s, o);
                q += __shfl_xor_sync(0xffffffffu, q, o);
            }
            float mu = s*(1.f/64.f);
            float var = q*(1.f/64.f) - mu*mu;
            float rs = rsqrtf(var + 1e-5f);
            float4 h;
            h.x = (a.x-mu)*rs*cb[64+c0  ] + cb[128+c0  ];
            h.y = (a.y-mu)*rs*cb[64+c0+1] + cb[128+c0+1];
            h.z = (a.z-mu)*rs*cb[64+c0+2] + cb[128+c0+2];
            h.w = (a.w-mu)*rs*cb[64+c0+3] + cb[128+c0+3];
            h.x *= sigf(h.x); h.y *= sigf(h.y); h.z *= sigf(h.z); h.w *= sigf(h.w);
            *(float4*)(s_H + rg*68 + c0) = h;
        }
        __syncthreads();
        // GEMM2: WL = H @ W2  (FFMA2, write g_wlc directly, stash wl0)
        {
            int rgr = tid>>6;
            int cc  = tid&63;
            unsigned long long acc[4][3];
            #pragma unroll
            for (int i = 0; i < 4; i++){ acc[i][0]=0ull; acc[i][1]=0ull; acc[i][2]=0ull; }
            const float* Wp0 = s_W2T + cc*68;
            const float* Wp1 = s_W2T + (cc+64)*68;
            const float* Wp2 = s_W2T + (cc+128)*68;
            #pragma unroll 4
            for (int k = 0; k < 64; k += 4){
                ulonglong2 w0 = *(const ulonglong2*)(Wp0 + k);
                ulonglong2 w1 = *(const ulonglong2*)(Wp1 + k);
                ulonglong2 w2 = *(const ulonglong2*)(Wp2 + k);
                ulonglong2 x0 = *(const ulonglong2*)(s_H + (rgr   )*68 + k);
                ulonglong2 x1 = *(const ulonglong2*)(s_H + (rgr+4 )*68 + k);
                ulonglong2 x2 = *(const ulonglong2*)(s_H + (rgr+8 )*68 + k);
                ulonglong2 x3 = *(const ulonglong2*)(s_H + (rgr+12)*68 + k);
                ffma2(acc[0][0], x0.x, w0.x); ffma2(acc[0][0], x0.y, w0.y);
                ffma2(acc[0][1], x0.x, w1.x); ffma2(acc[0][1], x0.y, w1.y);
                ffma2(acc[0][2], x0.x, w2.x); ffma2(acc[0][2], x0.y, w2.y);
                ffma2(acc[1][0], x1.x, w0.x); ffma2(acc[1][0], x1.y, w0.y);
                ffma2(acc[1][1], x1.x, w1.x); ffma2(acc[1][1], x1.y, w1.y);
                ffma2(acc[1][2], x1.x, w2.x); ffma2(acc[1][2], x1.y, w2.y);
                ffma2(acc[2][0], x2.x, w0.x); ffma2(acc[2][0], x2.y, w0.y);
                ffma2(acc[2][1], x2.x, w1.x); ffma2(acc[2][1], x2.y, w1.y);
                ffma2(acc[2][2], x2.x, w2.x); ffma2(acc[2][2], x2.y, w2.y);
                ffma2(acc[3][0], x3.x, w0.x); ffma2(acc[3][0], x3.y, w0.y);
                ffma2(acc[3][1], x3.x, w1.x); ffma2(acc[3][1], x3.y, w1.y);
                ffma2(acc[3][2], x3.x, w2.x); ffma2(acc[3][2], x3.y, w2.y);
            }
            #pragma unroll
            for (int i = 0; i < 4; i++){
                int r = rgr + i*4;
                #pragma unroll
                for (int j = 0; j < 3; j++){
                    float2 p = up2(acc[i][j]);
                    float v = p.x + p.y + cb[320 + cc + 64*j];
                    g_wlc[(size_t)(base+r)*192 + cc + 64*j] = v;
                    if (j == 0) s_wl0[r*68 + cc] = v;
                }
            }
        }
        __syncthreads();
        // M0 build (+ park to gmem for k_gate / k_edgeB)
        int dst;
        {
            int e = rg;
            int src = esrc[base+e]; dst = edst[base+e];
            float ea0 = eattr[(size_t)(base+e)*9];
            float4 xs = *(const float4*)(g_xs + (size_t)src*576 + c0);
            float4 xd = *(const float4*)(g_xd + (size_t)dst*576 + c0);
            float4 wl = *(const float4*)(s_wl0 + e*68 + c0);
            float4 m0;
            m0.x = (xs.x+xd.x)*ea0*wl.x; m0.y = (xs.y+xd.y)*ea0*wl.y;
            m0.z = (xs.z+xd.z)*ea0*wl.z; m0.w = (xs.w+xd.w)*ea0*wl.w;
            *(float4*)(s_M0 + e*68 + c0) = m0;
            *(float4*)(g_m0 + (size_t)(base+e)*64 + c0) = m0;
        }
        __syncthreads();
        // GEMM3: alpha logits -> softmax numerator w = exp(logit) (FFMA2)
        {
            unsigned long long q0=0ull,q1=0ull,q2=0ull,q3=0ull;
            const float* Xp = s_M0 + rg*68;
            #pragma unroll 4
            for (int k = 0; k < 64; k += 4){
                ulonglong2 x  = *(const ulonglong2*)(Xp + k);
                ulonglong2 w0 = *(const ulonglong2*)(Wap0 + k);
                ulonglong2 w1 = *(const ulonglong2*)(Wap1 + k);
                ulonglong2 w2 = *(const ulonglong2*)(Wap2 + k);
                ulonglong2 w3 = *(const ulonglong2*)(Wap3 + k);
                ffma2(q0, x.x, w0.x); ffma2(q0, x.y, w0.y);
                ffma2(q1, x.x, w1.x); ffma2(q1, x.y, w1.y);
                ffma2(q2, x.x, w2.x); ffma2(q2, x.y, w2.y);
                ffma2(q3, x.x, w3.x); ffma2(q3, x.y, w3.y);
            }
            float2 p0=up2(q0), p1=up2(q1), p2=up2(q2), p3=up2(q3);
            float4 a;
            a.x = p0.x+p0.y + cb[192+c0  ];
            a.y = p1.x+p1.y + cb[192+c0+1];
            a.z = p2.x+p2.y + cb[192+c0+2];
            a.w = p3.x+p3.y + cb[192+c0+3];
            a.x = 0.2f*a.x + 0.8f*a.x*sigf(a.x);
            a.y = 0.2f*a.y + 0.8f*a.y*sigf(a.y);
            a.z = 0.2f*a.z + 0.8f*a.z*sigf(a.z);
            a.w = 0.2f*a.w + 0.8f*a.w*sigf(a.w);
            float s4 = a.x*cb[256+c0] + a.y*cb[256+c0+1] + a.z*cb[256+c0+2] + a.w*cb[256+c0+3];
            float lg = s4 + __shfl_xor_sync(0xffffffffu, s4, 1);
            if ((tx & 1) == 0){
                int h = tx >> 1;
                float wexp = __expf(lg);
                g_logit[(size_t)(base+rg)*8 + h] = wexp;
                atomicAdd(&g_denom[dst*8 + h], wexp);
            }
        }
    }
}

// ================= K2b: gate = sigmoid(M0 @ Wg + bg) — dense FFMA2 GEMM ========
__global__ __launch_bounds__(256) void k_gate(
    const float* __restrict__ Wv, const float* __restrict__ bv)
{
    extern __shared__ float sm[];
    float* s_Wt = sm;             // [64][68] transposed gate cols
    float* s_X  = s_Wt + 64*68;   // [32][68]
    float* s_b  = s_X + 32*68;    // 64
    int tid = threadIdx.x;
    for (int t = tid; t < 4096; t += 256){
        int k = t>>6, c = t&63;
        s_Wt[c*68 + k] = Wv[k*128 + 64 + c];
    }
    if (tid < 64) s_b[tid] = bv[64 + tid];
    __syncthreads();

    int rgr = tid>>6;     // 0..3
    int cc  = tid&63;
    const float* Wc = s_Wt + cc*68;

    for (int base = blockIdx.x*32; base < NE; base += gridDim.x*32){
        __syncthreads();
        for (int i = tid; i < 512; i += 256){
            int e = i>>4, c4 = (i&15)*4;
            *(float4*)(s_X + e*68 + c4) = *(const float4*)(g_m0 + (size_t)(base+e)*64 + c4);
        }
        __syncthreads();
        unsigned long long acc[8];
        #pragma unroll
        for (int i = 0; i < 8; i++) acc[i] = 0ull;
        #pragma unroll 4
        for (int k = 0; k < 64; k += 4){
            ulonglong2 w = *(const ulonglong2*)(Wc + k);
            #pragma unroll
            for (int i = 0; i < 8; i++){
                ulonglong2 x = *(const ulonglong2*)(s_X + (rgr + 4*i)*68 + k);
                ffma2(acc[i], x.x, w.x);
                ffma2(acc[i], x.y, w.y);
            }
        }
        float bb = s_b[cc];
        #pragma unroll
        for (int i = 0; i < 8; i++){
            float2 p = up2(acc[i]);
            g_gate[(size_t)(base + rgr + 4*i)*64 + cc] = sigf(p.x + p.y + bb);
        }
    }
}

// ================= K3: value GEMM + weighted scatter, FFMA2, warp-per-edge ======
__global__ __launch_bounds__(256, 2) void k_edgeB(
    const float* __restrict__ eattr, const int* __restrict__ esrc,
    const int* __restrict__ edst,    const float* __restrict__ Wv,
    const float* __restrict__ bv)
{
    extern __shared__ float sm[];
    float* s_Wt = sm;                 // [64][68] transposed value cols
    float* s_X  = s_Wt + 64*68;       // [8 warps][9 rows][68]
    float* s_wl = s_X + 8*9*68;       // [8][192]
    float* s_ea = s_wl + 8*192;       // [8][12]
    float* s_sw = s_ea + 96;          // [8][8]
    float* s_bv = s_sw + 64;          // 64
    int tid = threadIdx.x;
    for (int t = tid; t < 4096; t += 256){
        int k = t>>6, c = t&63;
        s_Wt[c*68 + k] = Wv[k*128 + c];
    }
    if (tid < 64) s_bv[tid] = bv[tid];
    __syncthreads();

    int w = tid>>5, lane = tid&31;
    float* myX  = s_X  + w*9*68;
    float* mywl = s_wl + w*192;
    float* myea = s_ea + w*12;
    float* mysw = s_sw + w*8;
    const float* Wc0 = s_Wt + lane*68;
    const float* Wc1 = s_Wt + (lane+32)*68;
    int gw = blockIdx.x*8 + w;

    for (int e = gw; e < NE; e += 2368){
        int src = esrc[e], dst = edst[e];
        float gate0 = g_gate[(size_t)e*64 + lane];
        float gate1 = g_gate[(size_t)e*64 + lane + 32];
        #pragma unroll
        for (int t = lane; t < 48; t += 32){
            float4 v = *(const float4*)(g_wlc + (size_t)e*192 + t*4);
            *(float4*)(mywl + t*4) = v;
        }
        if (lane < 9) myea[lane] = eattr[(size_t)e*9 + lane];
        if (lane < 8) mysw[lane] = g_logit[(size_t)e*8 + lane];   // precomputed exp
        __syncwarp();
        // row 0: precomputed m0
        {
            float2 v = *(const float2*)(g_m0 + (size_t)e*64 + 2*lane);
            *(float2*)(myX + 2*lane) = v;
        }
        #pragma unroll
        for (int m = 1; m < 9; m++){
            int lsel = (m<4) ? 1 : 2;
            float2 a = *(const float2*)(g_xs + (size_t)src*576 + m*64 + 2*lane);
            float2 b = *(const float2*)(g_xd + (size_t)dst*576 + m*64 + 2*lane);
            float eam = myea[m];
            float2 wl2 = *(const float2*)(mywl + lsel*64 + 2*lane);
            float2 v; v.x = (a.x+b.x)*eam*wl2.x; v.y = (a.y+b.y)*eam*wl2.y;
            *(float2*)(myX + m*68 + 2*lane) = v;
        }
        __syncwarp();
        unsigned long long accv[9][2];
        #pragma unroll
        for (int m = 0; m < 9; m++){ accv[m][0] = 0ull; accv[m][1] = 0ull; }
        #pragma unroll 4
        for (int k = 0; k < 64; k += 4){
            ulonglong2 w0 = *(const ulonglong2*)(Wc0 + k);
            ulonglong2 w1 = *(const ulonglong2*)(Wc1 + k);
            #pragma unroll
            for (int m = 0; m < 9; m++){
                ulonglong2 x = *(const ulonglong2*)(myX + m*68 + k);
                ffma2(accv[m][0], x.x, w0.x); ffma2(accv[m][0], x.y, w0.y);
                ffma2(accv[m][1], x.x, w1.x); ffma2(accv[m][1], x.y, w1.y);
            }
        }
        __syncwarp();
        {
            float whA = mysw[lane>>3];
            float whB = mysw[(lane+32)>>3];
            #pragma unroll
            for (int m = 0; m < 9; m++){
                int lsel = (m==0) ? 0 : (m<4) ? 1 : 2;
                float2 vA = up2(accv[m][0]);
                float2 vB = up2(accv[m][1]);
                float yA = vA.x + vA.y;
                float yB = vB.x + vB.y;
                float oA, oB;
                if (m == 0){
                    yA += s_bv[lane]; yB += s_bv[lane+32];
                    oA = yA * sigf(yA); oB = yB * sigf(yB);
                } else {
                    oA = yA * gate0; oB = yB * gate1;
                }
                float eam = myea[m];
                oA *= eam * mywl[lsel*64 + lane]      * whA;
                oB *= eam * mywl[lsel*64 + lane + 32] * whB;
                myX[m*68 + lane]      = oA;
                myX[m*68 + lane + 32] = oB;
            }
        }
        __syncwarp();
        float* accp = g_acc + (size_t)dst*576;
        #pragma unroll
        for (int t = lane; t < 144; t += 32){
            int r = t>>4, c4 = (t&15)*4;
            float4 v = *(const float4*)(myX + r*68 + c4);
            atomicAdd((float4*)(accp + r*64 + c4), v);
        }
        __syncwarp();
    }
}

// ===== K4: normalize + projection, FFMA2 (8 nodes/iter) =========================
__global__ __launch_bounds__(256) void k_out(
    const float* __restrict__ Wp, const float* __restrict__ bp, float* __restrict__ out)
{
    extern __shared__ float sm[];
    float* s_WT = sm;              // [64 slots][68]
    float* s_X  = s_WT + 64*68;    // [80][68]
    float* s_b  = s_X + 80*68;     // 64
    float* s_inv= s_b + 64;        // 64
    int tid = threadIdx.x;
    for (int t = tid; t < 4096; t += 256){
        int k = t>>6, j = t&63;
        int slot = (j&3)*16 + (j>>2);
        s_WT[slot*68 + k] = Wp[t];
    }
    if (tid < 64) s_b[tid] = bp[tid];
    for (int t = tid; t < 8*68; t += 256) s_X[72*68 + t] = 0.f;
    __syncthreads();

    int rg = tid>>4, tx = tid&15, c0 = tx*4, r0 = rg*5;
    const float* Wp0 = s_WT + tx*68;
    const float* Wp1 = s_WT + (tx+16)*68;
    const float* Wp2 = s_WT + (tx+32)*68;
    const float* Wp3 = s_WT + (tx+48)*68;

    for (int base = blockIdx.x*8; base < NN; base += gridDim.x*8){
        __syncthreads();
        if (tid < 64){
            int e = tid>>3, h = tid&7;
            s_inv[tid] = 1.f/(g_denom[(base+e)*8 + h] + 1e-16f);
        }
        __syncthreads();
        for (int i = tid; i < 1152; i += 256){
            int n = i/144, rem = i - n*144;
            int row = n*9 + (rem>>4), c4 = (rem&15)*4;
            float inv = s_inv[n*8 + (c4>>3)];
            float4 v = *(const float4*)(g_acc + (size_t)(base+n)*576 + (rem>>4)*64 + c4);
            v.x *= inv; v.y *= inv; v.z *= inv; v.w *= inv;
            *(float4*)(s_X + row*68 + c4) = v;
        }
        __syncthreads();
        unsigned long long q[5][4];
        #pragma unroll
        for (int r = 0; r < 5; r++)
            #pragma unroll
            for (int i = 0; i < 4; i++) q[r][i] = 0ull;
        const float* Xp = s_X + r0*68;
        #pragma unroll 4
        for (int k = 0; k < 64; k += 4){
            ulonglong2 w0 = *(const ulonglong2*)(Wp0 + k);
            ulonglong2 w1 = *(const ulonglong2*)(Wp1 + k);
            ulonglong2 w2 = *(const ulonglong2*)(Wp2 + k);
            ulonglong2 w3 = *(const ulonglong2*)(Wp3 + k);
            #pragma unroll
            for (int r = 0; r < 5; r++){
                ulonglong2 x = *(const ulonglong2*)(Xp + r*68 + k);
                ffma2(q[r][0], x.x, w0.x); ffma2(q[r][0], x.y, w0.y);
                ffma2(q[r][1], x.x, w1.x); ffma2(q[r][1], x.y, w1.y);
                ffma2(q[r][2], x.x, w2.x); ffma2(q[r][2], x.y, w2.y);
                ffma2(q[r][3], x.x, w3.x); ffma2(q[r][3], x.y, w3.y);
            }
        }
        #pragma unroll
        for (int i = 0; i < 5; i++){
            int r = r0 + i;
            if (r < 72){
                int n = base + r/9, m = r%9;
                float2 p0 = up2(q[i][0]), p1 = up2(q[i][1]);
                float2 p2 = up2(q[i][2]), p3 = up2(q[i][3]);
                float4 v;
                v.x = p0.x+p0.y; v.y = p1.x+p1.y; v.z = p2.x+p2.y; v.w = p3.x+p3.y;
                if (m == 0){
                    v.x += s_b[c0]; v.y += s_b[c0+1]; v.z += s_b[c0+2]; v.w += s_b[c0+3];
                }
                *(float4*)(out + (size_t)n*576 + m*64 + c0) = v;
            }
        }
    }
}

extern "C" void kernel_launch(void* const* d_in, const int* in_sizes, int n_in,
                              void* d_out, int out_size)
{
    const float* node_input = (const float*)d_in[0];
    const float* edge_attr  = (const float*)d_in[1];
    const float* edge_scal  = (const float*)d_in[2];
    const float* W_src = (const float*)d_in[3];
    const float* b_src = (const float*)d_in[4];
    const float* W_dst = (const float*)d_in[5];
    const float* rW1   = (const float*)d_in[6];
    const float* rb1   = (const float*)d_in[7];
    const float* lng   = (const float*)d_in[8];
    const float* lnb   = (const float*)d_in[9];
    const float* rW2   = (const float*)d_in[10];
    const float* roff  = (const float*)d_in[11];
    const float* Wa    = (const float*)d_in[12];
    const float* ba    = (const float*)d_in[13];
    const float* adot  = (const float*)d_in[14];
    const float* Wv    = (const float*)d_in[15];
    const float* bv    = (const float*)d_in[16];
    const float* Wp    = (const float*)d_in[17];
    const float* bp    = (const float*)d_in[18];
    const int*   esrc  = (const int*)d_in[19];
    const int*   edst  = (const int*)d_in[20];
    float* out = (float*)d_out;

    const int smem_node = (128*68 + 40*68 + 64) * 4;
    const int smem_eA   = (64*68*2 + 192*68 + 512 + 16*68*4) * 4;
    const int smem_gate = (64*68 + 32*68 + 64) * 4;
    const int smem_eB   = (64*68 + 8*9*68 + 8*192 + 96 + 64 + 64) * 4;
    const int smem_out  = (64*68 + 80*68 + 64 + 64) * 4;

    cudaFuncSetAttribute(k_node,  cudaFuncAttributeMaxDynamicSharedMemorySize, smem_node);
    cudaFuncSetAttribute(k_edgeA, cudaFuncAttributeMaxDynamicSharedMemorySize, smem_eA);
    cudaFuncSetAttribute(k_gate,  cudaFuncAttributeMaxDynamicSharedMemorySize, smem_gate);
    cudaFuncSetAttribute(k_edgeB, cudaFuncAttributeMaxDynamicSharedMemorySize, smem_eB);
    cudaFuncSetAttribute(k_out,   cudaFuncAttributeMaxDynamicSharedMemorySize, smem_out);

    k_init<<<2048, 256>>>();
    k_node<<<296, 256, smem_node>>>(node_input, W_src, b_src, W_dst);
    k_edgeA<<<296, 256, smem_eA>>>(edge_scal, edge_attr, esrc, edst,
                                   rW1, rb1, lng, lnb, rW2, roff, Wa, ba, adot);
    k_gate<<<592, 256, smem_gate>>>(Wv, bv);
    k_edgeB<<<296, 256, smem_eB>>>(edge_attr, esrc, edst, Wv, bv);
    k_out<<<296, 256, smem_out>>>(Wp, bp, out);
}

// round 15
// speedup vs baseline: 1.2190x; 1.0029x over previous
#include <cuda_runtime.h>
#include <math.h>

#define NN 10000
#define NE 160000
#define MM 9
#define CC 64
#define HH 8

// ---------------- scratch (static device globals; no allocation) ----------------
__device__ float    g_xs[NN*MM*CC];        // node src-linear   (23 MB)
__device__ float    g_xd[NN*MM*CC];        // node dst-linear   (23 MB)
__device__ float    g_wlc[(size_t)NE*192]; // radial weights    (123 MB)
__device__ float    g_m0[(size_t)NE*64];   // msg row 0         (41 MB)
__device__ float    g_gate[(size_t)NE*64]; // sigmoid(gate)     (41 MB)
__device__ float    g_logit[NE*HH];        // exp(logit) (unnormalized softmax w)
__device__ float    g_denom[NN*HH];
__device__ float    g_acc[NN*MM*CC];

__device__ __forceinline__ float sigf(float x){ return 1.f/(1.f + __expf(-x)); }

// packed fp32x2 FMA: d = a*b + d
__device__ __forceinline__ void ffma2(unsigned long long& d,
                                      unsigned long long a,
                                      unsigned long long b){
    asm("fma.rn.f32x2 %0, %1, %2, %0;" : "+l"(d) : "l"(a), "l"(b));
}
__device__ __forceinline__ float2 up2(unsigned long long v){
    float2 r; asm("mov.b64 {%0,%1}, %2;" : "=f"(r.x), "=f"(r.y) : "l"(v)); return r;
}

// ===== K1: node linear, FFMA2 (4 nodes -> X[40x64] @ W[64x128]) =================
// Also zeroes g_acc / g_denom (k_init folded in): k_node completes before any
// kernel reads or accumulates into those buffers.
__global__ __launch_bounds__(256) void k_node(
    const float* __restrict__ xin, const float* __restrict__ Ws,
    const float* __restrict__ bs,  const float* __restrict__ Wd)
{
    extern __shared__ float sm[];
    float* s_WT = sm;              // [128 slots][68]
    float* s_X  = s_WT + 128*68;   // [40][68]
    float* s_b  = s_X + 40*68;     // 64
    int tid = threadIdx.x;
    int gtid = blockIdx.x*256 + tid;
    // ---- folded init: zero accumulators ----
    {
        float4 z = make_float4(0.f,0.f,0.f,0.f);
        float4* accp = (float4*)g_acc;
        for (int t = gtid; t < NN*MM*CC/4; t += 296*256) accp[t] = z;
        for (int t = gtid; t < NN*HH; t += 296*256) g_denom[t] = 0.f;
    }
    for (int t = tid; t < 8192; t += 256){
        int k = t>>7, c = t&127;
        float v = (c < 64) ? Ws[k*64 + c] : Wd[k*64 + (c-64)];
        int slot = (c&3)*32 + (c>>2);
        s_WT[slot*68 + k] = v;
    }
    if (tid < 64) s_b[tid] = bs[tid];
    for (int t = tid; t < 4*68; t += 256) s_X[36*68 + t] = 0.f;
    __syncthreads();

    int rg = tid>>5;
    int tx = tid&31;
    int c0 = tx*4;
    int r0 = rg*5;
    const float* Wp0 = s_WT + tx*68;
    const float* Wp1 = s_WT + (tx+32)*68;
    const float* Wp2 = s_WT + (tx+64)*68;
    const float* Wp3 = s_WT + (tx+96)*68;

    for (int base = blockIdx.x*4; base < NN; base += gridDim.x*4){
        __syncthreads();
        for (int i = tid; i < 576; i += 256){
            int n = i/144, rem = i - n*144;
            int row = n*9 + (rem>>4), c4 = (rem&15)*4;
            *(float4*)(s_X + row*68 + c4) =
                *(const float4*)(xin + (size_t)(base+n)*576 + (rem>>4)*64 + c4);
        }
        __syncthreads();
        unsigned long long q[5][4];
        #pragma unroll
        for (int r = 0; r < 5; r++)
            #pragma unroll
            for (int i = 0; i < 4; i++) q[r][i] = 0ull;
        const float* Xp = s_X + r0*68;
        #pragma unroll 4
        for (int k = 0; k < 64; k += 4){
            ulonglong2 w0 = *(const ulonglong2*)(Wp0 + k);
            ulonglong2 w1 = *(const ulonglong2*)(Wp1 + k);
            ulonglong2 w2 = *(const ulonglong2*)(Wp2 + k);
            ulonglong2 w3 = *(const ulonglong2*)(Wp3 + k);
            #pragma unroll
            for (int r = 0; r < 5; r++){
                ulonglong2 x = *(const ulonglong2*)(Xp + r*68 + k);
                ffma2(q[r][0], x.x, w0.x); ffma2(q[r][0], x.y, w0.y);
                ffma2(q[r][1], x.x, w1.x); ffma2(q[r][1], x.y, w1.y);
                ffma2(q[r][2], x.x, w2.x); ffma2(q[r][2], x.y, w2.y);
                ffma2(q[r][3], x.x, w3.x); ffma2(q[r][3], x.y, w3.y);
            }
        }
        #pragma unroll
        for (int i = 0; i < 5; i++){
            int r = r0 + i;
            if (r < 36){
                int n = base + r/9, m = r%9;
                float2 p0 = up2(q[i][0]), p1 = up2(q[i][1]);
                float2 p2 = up2(q[i][2]), p3 = up2(q[i][3]);
                float4 v;
                v.x = p0.x+p0.y; v.y = p1.x+p1.y; v.z = p2.x+p2.y; v.w = p3.x+p3.y;
                if (m == 0 && c0 < 64){
                    v.x += s_b[c0]; v.y += s_b[c0+1]; v.z += s_b[c0+2]; v.w += s_b[c0+3];
                }
                if (c0 < 64) *(float4*)(g_xs + (size_t)n*576 + m*64 + c0) = v;
                else         *(float4*)(g_xd + (size_t)n*576 + m*64 + (c0-64)) = v;
            }
        }
    }
}

// ===== K2: radial MLP + softmax weights, FFMA2 (16 edges/iter, 256t) ============
__global__ __launch_bounds__(256) void k_edgeA(
    const float* __restrict__ esc, const float* __restrict__ eattr,
    const int* __restrict__ esrc,  const int* __restrict__ edst,
    const float* __restrict__ W1,  const float* __restrict__ b1,
    const float* __restrict__ lng, const float* __restrict__ lnb,
    const float* __restrict__ W2,  const float* __restrict__ off,
    const float* __restrict__ Wa,  const float* __restrict__ ba,
    const float* __restrict__ adot)
{
    extern __shared__ float sm[];
    float* s_W1T = sm;                // [64 slots][68]
    float* s_WaT = s_W1T + 64*68;     // [64 slots][68]
    float* s_W2T = s_WaT + 64*68;     // [192 cols][68]
    float* cb    = s_W2T + 192*68;    // b1|lng|lnb|ba|adot|off = 512
    float* s_S   = cb + 512;          // [16][68]
    float* s_H   = s_S + 16*68;       // [16][68]
    float* s_M0  = s_H + 16*68;       // [16][68]
    float* s_wl0 = s_M0 + 16*68;      // [16][68]
    int tid = threadIdx.x;
    for (int t = tid; t < 4096; t += 256){
        int k = t>>6, j = t&63;
        int slot = (j&3)*16 + (j>>2);
        s_W1T[slot*68 + k] = W1[t];
        s_WaT[slot*68 + k] = Wa[t];
    }
    for (int t = tid; t < 12288; t += 256){
        int k = t/192, c = t - k*192;
        s_W2T[c*68 + k] = W2[t];
    }
    if (tid < 64){
        cb[tid] = b1[tid]; cb[64+tid] = lng[tid]; cb[128+tid] = lnb[tid];
        cb[192+tid] = ba[tid]; cb[256+tid] = adot[tid];
    }
    for (int t = tid; t < 192; t += 256) cb[320+t] = off[t];
    __syncthreads();

    int rg = tid>>4;            // 0..15 (edge row)
    int tx = tid&15;
    int c0 = tx*4;
    const float* W1p0 = s_W1T + tx*68;
    const float* W1p1 = s_W1T + (tx+16)*68;
    const float* W1p2 = s_W1T + (tx+32)*68;
    const float* W1p3 = s_W1T + (tx+48)*68;
    const float* Wap0 = s_WaT + tx*68;
    const float* Wap1 = s_WaT + (tx+16)*68;
    const float* Wap2 = s_WaT + (tx+32)*68;
    const float* Wap3 = s_WaT + (tx+48)*68;

    for (int base = blockIdx.x*16; base < NE; base += gridDim.x*16){
        __syncthreads();
        for (int i = tid; i < 16*16; i += 256){
            int e = i>>4, c4 = (i&15)*4;
            *(float4*)(s_S + e*68 + c4) = *(const float4*)(esc + (size_t)(base+e)*64 + c4);
        }
        __syncthreads();
        // GEMM1: H = S @ W1  (FFMA2)
        {
            unsigned long long q0=0ull,q1=0ull,q2=0ull,q3=0ull;
            const float* Xp = s_S + rg*68;
            #pragma unroll 4
            for (int k = 0; k < 64; k += 4){
                ulonglong2 x  = *(const ulonglong2*)(Xp + k);
                ulonglong2 w0 = *(const ulonglong2*)(W1p0 + k);
                ulonglong2 w1 = *(const ulonglong2*)(W1p1 + k);
                ulonglong2 w2 = *(const ulonglong2*)(W1p2 + k);
                ulonglong2 w3 = *(const ulonglong2*)(W1p3 + k);
                ffma2(q0, x.x, w0.x); ffma2(q0, x.y, w0.y);
                ffma2(q1, x.x, w1.x); ffma2(q1, x.y, w1.y);
                ffma2(q2, x.x, w2.x); ffma2(q2, x.y, w2.y);
                ffma2(q3, x.x, w3.x); ffma2(q3, x.y, w3.y);
            }
            float2 p0=up2(q0), p1=up2(q1), p2=up2(q2), p3=up2(q3);
            float4 a;
            a.x = p0.x+p0.y + cb[c0  ];
            a.y = p1.x+p1.y + cb[c0+1];
            a.z = p2.x+p2.y + cb[c0+2];
            a.w = p3.x+p3.y + cb[c0+3];
            float s = a.x+a.y+a.z+a.w;
            float q = a.x*a.x+a.y*a.y+a.z*a.z+a.w*a.w;
            #pragma unroll
            for (int o = 8; o > 0; o >>= 1){
                s += __shfl_xor_sync(0xffffffffu, s, o);
                q += __shfl_xor_sync(0xffffffffu, q, o);
            }
            float mu = s*(1.f/64.f);
            float var = q*(1.f/64.f) - mu*mu;
            float rs = rsqrtf(var + 1e-5f);
            float4 h;
            h.x = (a.x-mu)*rs*cb[64+c0  ] + cb[128+c0  ];
            h.y = (a.y-mu)*rs*cb[64+c0+1] + cb[128+c0+1];
            h.z = (a.z-mu)*rs*cb[64+c0+2] + cb[128+c0+2];
            h.w = (a.w-mu)*rs*cb[64+c0+3] + cb[128+c0+3];
            h.x *= sigf(h.x); h.y *= sigf(h.y); h.z *= sigf(h.z); h.w *= sigf(h.w);
            *(float4*)(s_H + rg*68 + c0) = h;
        }
        __syncthreads();
        // GEMM2: WL = H @ W2  (FFMA2, write g_wlc directly, stash wl0)
        {
            int rgr = tid>>6;
            int cc  = tid&63;
            unsigned long long acc[4][3];
            #pragma unroll
            for (int i = 0; i < 4; i++){ acc[i][0]=0ull; acc[i][1]=0ull; acc[i][2]=0ull; }
            const float* Wp0 = s_W2T + cc*68;
            const float* Wp1 = s_W2T + (cc+64)*68;
            const float* Wp2 = s_W2T + (cc+128)*68;
            #pragma unroll 4
            for (int k = 0; k < 64; k += 4){
                ulonglong2 w0 = *(const ulonglong2*)(Wp0 + k);
                ulonglong2 w1 = *(const ulonglong2*)(Wp1 + k);
                ulonglong2 w2 = *(const ulonglong2*)(Wp2 + k);
                ulonglong2 x0 = *(const ulonglong2*)(s_H + (rgr   )*68 + k);
                ulonglong2 x1 = *(const ulonglong2*)(s_H + (rgr+4 )*68 + k);
                ulonglong2 x2 = *(const ulonglong2*)(s_H + (rgr+8 )*68 + k);
                ulonglong2 x3 = *(const ulonglong2*)(s_H + (rgr+12)*68 + k);
                ffma2(acc[0][0], x0.x, w0.x); ffma2(acc[0][0], x0.y, w0.y);
                ffma2(acc[0][1], x0.x, w1.x); ffma2(acc[0][1], x0.y, w1.y);
                ffma2(acc[0][2], x0.x, w2.x); ffma2(acc[0][2], x0.y, w2.y);
                ffma2(acc[1][0], x1.x, w0.x); ffma2(acc[1][0], x1.y, w0.y);
                ffma2(acc[1][1], x1.x, w1.x); ffma2(acc[1][1], x1.y, w1.y);
                ffma2(acc[1][2], x1.x, w2.x); ffma2(acc[1][2], x1.y, w2.y);
                ffma2(acc[2][0], x2.x, w0.x); ffma2(acc[2][0], x2.y, w0.y);
                ffma2(acc[2][1], x2.x, w1.x); ffma2(acc[2][1], x2.y, w1.y);
                ffma2(acc[2][2], x2.x, w2.x); ffma2(acc[2][2], x2.y, w2.y);
                ffma2(acc[3][0], x3.x, w0.x); ffma2(acc[3][0], x3.y, w0.y);
                ffma2(acc[3][1], x3.x, w1.x); ffma2(acc[3][1], x3.y, w1.y);
                ffma2(acc[3][2], x3.x, w2.x); ffma2(acc[3][2], x3.y, w2.y);
            }
            #pragma unroll
            for (int i = 0; i < 4; i++){
                int r = rgr + i*4;
                #pragma unroll
                for (int j = 0; j < 3; j++){
                    float2 p = up2(acc[i][j]);
                    float v = p.x + p.y + cb[320 + cc + 64*j];
                    g_wlc[(size_t)(base+r)*192 + cc + 64*j] = v;
                    if (j == 0) s_wl0[r*68 + cc] = v;
                }
            }
        }
        __syncthreads();
        // M0 build (+ park to gmem for k_gate / k_edgeB)
        int dst;
        {
            int e = rg;
            int src = esrc[base+e]; dst = edst[base+e];
            float ea0 = eattr[(size_t)(base+e)*9];
            float4 xs = *(const float4*)(g_xs + (size_t)src*576 + c0);
            float4 xd = *(const float4*)(g_xd + (size_t)dst*576 + c0);
            float4 wl = *(const float4*)(s_wl0 + e*68 + c0);
            float4 m0;
            m0.x = (xs.x+xd.x)*ea0*wl.x; m0.y = (xs.y+xd.y)*ea0*wl.y;
            m0.z = (xs.z+xd.z)*ea0*wl.z; m0.w = (xs.w+xd.w)*ea0*wl.w;
            *(float4*)(s_M0 + e*68 + c0) = m0;
            *(float4*)(g_m0 + (size_t)(base+e)*64 + c0) = m0;
        }
        __syncthreads();
        // GEMM3: alpha logits -> softmax numerator w = exp(logit) (FFMA2)
        {
            unsigned long long q0=0ull,q1=0ull,q2=0ull,q3=0ull;
            const float* Xp = s_M0 + rg*68;
            #pragma unroll 4
            for (int k = 0; k < 64; k += 4){
                ulonglong2 x  = *(const ulonglong2*)(Xp + k);
                ulonglong2 w0 = *(const ulonglong2*)(Wap0 + k);
                ulonglong2 w1 = *(const ulonglong2*)(Wap1 + k);
                ulonglong2 w2 = *(const ulonglong2*)(Wap2 + k);
                ulonglong2 w3 = *(const ulonglong2*)(Wap3 + k);
                ffma2(q0, x.x, w0.x); ffma2(q0, x.y, w0.y);
                ffma2(q1, x.x, w1.x); ffma2(q1, x.y, w1.y);
                ffma2(q2, x.x, w2.x); ffma2(q2, x.y, w2.y);
                ffma2(q3, x.x, w3.x); ffma2(q3, x.y, w3.y);
            }
            float2 p0=up2(q0), p1=up2(q1), p2=up2(q2), p3=up2(q3);
            float4 a;
            a.x = p0.x+p0.y + cb[192+c0  ];
            a.y = p1.x+p1.y + cb[192+c0+1];
            a.z = p2.x+p2.y + cb[192+c0+2];
            a.w = p3.x+p3.y + cb[192+c0+3];
            a.x = 0.2f*a.x + 0.8f*a.x*sigf(a.x);
            a.y = 0.2f*a.y + 0.8f*a.y*sigf(a.y);
            a.z = 0.2f*a.z + 0.8f*a.z*sigf(a.z);
            a.w = 0.2f*a.w + 0.8f*a.w*sigf(a.w);
            float s4 = a.x*cb[256+c0] + a.y*cb[256+c0+1] + a.z*cb[256+c0+2] + a.w*cb[256+c0+3];
            float lg = s4 + __shfl_xor_sync(0xffffffffu, s4, 1);
            if ((tx & 1) == 0){
                int h = tx >> 1;
                float wexp = __expf(lg);
                g_logit[(size_t)(base+rg)*8 + h] = wexp;
                atomicAdd(&g_denom[dst*8 + h], wexp);
            }
        }
    }
}

// ================= K2b: gate = sigmoid(M0 @ Wg + bg) — dense FFMA2 GEMM ========
__global__ __launch_bounds__(256) void k_gate(
    const float* __restrict__ Wv, const float* __restrict__ bv)
{
    extern __shared__ float sm[];
    float* s_Wt = sm;             // [64][68] transposed gate cols
    float* s_X  = s_Wt + 64*68;   // [32][68]
    float* s_b  = s_X + 32*68;    // 64
    int tid = threadIdx.x;
    for (int t = tid; t < 4096; t += 256){
        int k = t>>6, c = t&63;
        s_Wt[c*68 + k] = Wv[k*128 + 64 + c];
    }
    if (tid < 64) s_b[tid] = bv[64 + tid];
    __syncthreads();

    int rgr = tid>>6;     // 0..3
    int cc  = tid&63;
    const float* Wc = s_Wt + cc*68;

    for (int base = blockIdx.x*32; base < NE; base += gridDim.x*32){
        __syncthreads();
        for (int i = tid; i < 512; i += 256){
            int e = i>>4, c4 = (i&15)*4;
            *(float4*)(s_X + e*68 + c4) = *(const float4*)(g_m0 + (size_t)(base+e)*64 + c4);
        }
        __syncthreads();
        unsigned long long acc[8];
        #pragma unroll
        for (int i = 0; i < 8; i++) acc[i] = 0ull;
        #pragma unroll 4
        for (int k = 0; k < 64; k += 4){
            ulonglong2 w = *(const ulonglong2*)(Wc + k);
            #pragma unroll
            for (int i = 0; i < 8; i++){
                ulonglong2 x = *(const ulonglong2*)(s_X + (rgr + 4*i)*68 + k);
                ffma2(acc[i], x.x, w.x);
                ffma2(acc[i], x.y, w.y);
            }
        }
        float bb = s_b[cc];
        #pragma unroll
        for (int i = 0; i < 8; i++){
            float2 p = up2(acc[i]);
            g_gate[(size_t)(base + rgr + 4*i)*64 + cc] = sigf(p.x + p.y + bb);
        }
    }
}

// ================= K3: value GEMM + weighted scatter, FFMA2, warp-per-edge ======
__global__ __launch_bounds__(256, 2) void k_edgeB(
    const float* __restrict__ eattr, const int* __restrict__ esrc,
    const int* __restrict__ edst,    const float* __restrict__ Wv,
    const float* __restrict__ bv)
{
    extern __shared__ float sm[];
    float* s_Wt = sm;                 // [64][68] transposed value cols
    float* s_X  = s_Wt + 64*68;       // [8 warps][9 rows][68]
    float* s_wl = s_X + 8*9*68;       // [8][192]
    float* s_ea = s_wl + 8*192;       // [8][12]
    float* s_sw = s_ea + 96;          // [8][8]
    float* s_bv = s_sw + 64;          // 64
    int tid = threadIdx.x;
    for (int t = tid; t < 4096; t += 256){
        int k = t>>6, c = t&63;
        s_Wt[c*68 + k] = Wv[k*128 + c];
    }
    if (tid < 64) s_bv[tid] = bv[tid];
    __syncthreads();

    int w = tid>>5, lane = tid&31;
    float* myX  = s_X  + w*9*68;
    float* mywl = s_wl + w*192;
    float* myea = s_ea + w*12;
    float* mysw = s_sw + w*8;
    const float* Wc0 = s_Wt + lane*68;
    const float* Wc1 = s_Wt + (lane+32)*68;
    int gw = blockIdx.x*8 + w;

    for (int e = gw; e < NE; e += 2368){
        int src = esrc[e], dst = edst[e];
        float gate0 = g_gate[(size_t)e*64 + lane];
        float gate1 = g_gate[(size_t)e*64 + lane + 32];
        #pragma unroll
        for (int t = lane; t < 48; t += 32){
            float4 v = *(const float4*)(g_wlc + (size_t)e*192 + t*4);
            *(float4*)(mywl + t*4) = v;
        }
        if (lane < 9) myea[lane] = eattr[(size_t)e*9 + lane];
        if (lane < 8) mysw[lane] = g_logit[(size_t)e*8 + lane];   // precomputed exp
        __syncwarp();
        // row 0: precomputed m0
        {
            float2 v = *(const float2*)(g_m0 + (size_t)e*64 + 2*lane);
            *(float2*)(myX + 2*lane) = v;
        }
        #pragma unroll
        for (int m = 1; m < 9; m++){
            int lsel = (m<4) ? 1 : 2;
            float2 a = *(const float2*)(g_xs + (size_t)src*576 + m*64 + 2*lane);
            float2 b = *(const float2*)(g_xd + (size_t)dst*576 + m*64 + 2*lane);
            float eam = myea[m];
            float2 wl2 = *(const float2*)(mywl + lsel*64 + 2*lane);
            float2 v; v.x = (a.x+b.x)*eam*wl2.x; v.y = (a.y+b.y)*eam*wl2.y;
            *(float2*)(myX + m*68 + 2*lane) = v;
        }
        __syncwarp();
        unsigned long long accv[9][2];
        #pragma unroll
        for (int m = 0; m < 9; m++){ accv[m][0] = 0ull; accv[m][1] = 0ull; }
        #pragma unroll 4
        for (int k = 0; k < 64; k += 4){
            ulonglong2 w0 = *(const ulonglong2*)(Wc0 + k);
            ulonglong2 w1 = *(const ulonglong2*)(Wc1 + k);
            #pragma unroll
            for (int m = 0; m < 9; m++){
                ulonglong2 x = *(const ulonglong2*)(myX + m*68 + k);
                ffma2(accv[m][0], x.x, w0.x); ffma2(accv[m][0], x.y, w0.y);
                ffma2(accv[m][1], x.x, w1.x); ffma2(accv[m][1], x.y, w1.y);
            }
        }
        __syncwarp();
        {
            float whA = mysw[lane>>3];
            float whB = mysw[(lane+32)>>3];
            #pragma unroll
            for (int m = 0; m < 9; m++){
                int lsel = (m==0) ? 0 : (m<4) ? 1 : 2;
                float2 vA = up2(accv[m][0]);
                float2 vB = up2(accv[m][1]);
                float yA = vA.x + vA.y;
                float yB = vB.x + vB.y;
                float oA, oB;
                if (m == 0){
                    yA += s_bv[lane]; yB += s_bv[lane+32];
                    oA = yA * sigf(yA); oB = yB * sigf(yB);
                } else {
                    oA = yA * gate0; oB = yB * gate1;
                }
                float eam = myea[m];
                oA *= eam * mywl[lsel*64 + lane]      * whA;
                oB *= eam * mywl[lsel*64 + lane + 32] * whB;
                myX[m*68 + lane]      = oA;
                myX[m*68 + lane + 32] = oB;
            }
        }
        __syncwarp();
        float* accp = g_acc + (size_t)dst*576;
        #pragma unroll
        for (int t = lane; t < 144; t += 32){
            int r = t>>4, c4 = (t&15)*4;
            float4 v = *(const float4*)(myX + r*68 + c4);
            atomicAdd((float4*)(accp + r*64 + c4), v);
        }
        __syncwarp();
    }
}

// ===== K4: normalize + projection, FFMA2 (8 nodes/iter) =========================
__global__ __launch_bounds__(256) void k_out(
    const float* __restrict__ Wp, const float* __restrict__ bp, float* __restrict__ out)
{
    extern __shared__ float sm[];
    float* s_WT = sm;              // [64 slots][68]
    float* s_X  = s_WT + 64*68;    // [80][68]
    float* s_b  = s_X + 80*68;     // 64
    float* s_inv= s_b + 64;        // 64
    int tid = threadIdx.x;
    for (int t = tid; t < 4096; t += 256){
        int k = t>>6, j = t&63;
        int slot = (j&3)*16 + (j>>2);
        s_WT[slot*68 + k] = Wp[t];
    }
    if (tid < 64) s_b[tid] = bp[tid];
    for (int t = tid; t < 8*68; t += 256) s_X[72*68 + t] = 0.f;
    __syncthreads();

    int rg = tid>>4, tx = tid&15, c0 = tx*4, r0 = rg*5;
    const float* Wp0 = s_WT + tx*68;
    const float* Wp1 = s_WT + (tx+16)*68;
    const float* Wp2 = s_WT + (tx+32)*68;
    const float* Wp3 = s_WT + (tx+48)*68;

    for (int base = blockIdx.x*8; base < NN; base += gridDim.x*8){
        __syncthreads();
        if (tid < 64){
            int e = tid>>3, h = tid&7;
            s_inv[tid] = 1.f/(g_denom[(base+e)*8 + h] + 1e-16f);
        }
        __syncthreads();
        for (int i = tid; i < 1152; i += 256){
            int n = i/144, rem = i - n*144;
            int row = n*9 + (rem>>4), c4 = (rem&15)*4;
            float inv = s_inv[n*8 + (c4>>3)];
            float4 v = *(const float4*)(g_acc + (size_t)(base+n)*576 + (rem>>4)*64 + c4);
            v.x *= inv; v.y *= inv; v.z *= inv; v.w *= inv;
            *(float4*)(s_X + row*68 + c4) = v;
        }
        __syncthreads();
        unsigned long long q[5][4];
        #pragma unroll
        for (int r = 0; r < 5; r++)
            #pragma unroll
            for (int i = 0; i < 4; i++) q[r][i] = 0ull;
        const float* Xp = s_X + r0*68;
        #pragma unroll 4
        for (int k = 0; k < 64; k += 4){
            ulonglong2 w0 = *(const ulonglong2*)(Wp0 + k);
            ulonglong2 w1 = *(const ulonglong2*)(Wp1 + k);
            ulonglong2 w2 = *(const ulonglong2*)(Wp2 + k);
            ulonglong2 w3 = *(const ulonglong2*)(Wp3 + k);
            #pragma unroll
            for (int r = 0; r < 5; r++){
                ulonglong2 x = *(const ulonglong2*)(Xp + r*68 + k);
                ffma2(q[r][0], x.x, w0.x); ffma2(q[r][0], x.y, w0.y);
                ffma2(q[r][1], x.x, w1.x); ffma2(q[r][1], x.y, w1.y);
                ffma2(q[r][2], x.x, w2.x); ffma2(q[r][2], x.y, w2.y);
                ffma2(q[r][3], x.x, w3.x); ffma2(q[r][3], x.y, w3.y);
            }
        }
        #pragma unroll
        for (int i = 0; i < 5; i++){
            int r = r0 + i;
            if (r < 72){
                int n = base + r/9, m = r%9;
                float2 p0 = up2(q[i][0]), p1 = up2(q[i][1]);
                float2 p2 = up2(q[i][2]), p3 = up2(q[i][3]);
                float4 v;
                v.x = p0.x+p0.y; v.y = p1.x+p1.y; v.z = p2.x+p2.y; v.w = p3.x+p3.y;
                if (m == 0){
                    v.x += s_b[c0]; v.y += s_b[c0+1]; v.z += s_b[c0+2]; v.w += s_b[c0+3];
                }
                *(float4*)(out + (size_t)n*576 + m*64 + c0) = v;
            }
        }
    }
}

extern "C" void kernel_launch(void* const* d_in, const int* in_sizes, int n_in,
                              void* d_out, int out_size)
{
    const float* node_input = (const float*)d_in[0];
    const float* edge_attr  = (const float*)d_in[1];
    const float* edge_scal  = (const float*)d_in[2];
    const float* W_src = (const float*)d_in[3];
    const float* b_src = (const float*)d_in[4];
    const float* W_dst = (const float*)d_in[5];
    const float* rW1   = (const float*)d_in[6];
    const float* rb1   = (const float*)d_in[7];
    const float* lng   = (const float*)d_in[8];
    const float* lnb   = (const float*)d_in[9];
    const float* rW2   = (const float*)d_in[10];
    const float* roff  = (const float*)d_in[11];
    const float* Wa    = (const float*)d_in[12];
    const float* ba    = (const float*)d_in[13];
    const float* adot  = (const float*)d_in[14];
    const float* Wv    = (const float*)d_in[15];
    const float* bv    = (const float*)d_in[16];
    const float* Wp    = (const float*)d_in[17];
    const float* bp    = (const float*)d_in[18];
    const int*   esrc  = (const int*)d_in[19];
    const int*   edst  = (const int*)d_in[20];
    float* out = (float*)d_out;

    const int smem_node = (128*68 + 40*68 + 64) * 4;
    const int smem_eA   = (64*68*2 + 192*68 + 512 + 16*68*4) * 4;
    const int smem_gate = (64*68 + 32*68 + 64) * 4;
    const int smem_eB   = (64*68 + 8*9*68 + 8*192 + 96 + 64 + 64) * 4;
    const int smem_out  = (64*68 + 80*68 + 64 + 64) * 4;

    cudaFuncSetAttribute(k_node,  cudaFuncAttributeMaxDynamicSharedMemorySize, smem_node);
    cudaFuncSetAttribute(k_edgeA, cudaFuncAttributeMaxDynamicSharedMemorySize, smem_eA);
    cudaFuncSetAttribute(k_gate,  cudaFuncAttributeMaxDynamicSharedMemorySize, smem_gate);
    cudaFuncSetAttribute(k_edgeB, cudaFuncAttributeMaxDynamicSharedMemorySize, smem_eB);
    cudaFuncSetAttribute(k_out,   cudaFuncAttributeMaxDynamicSharedMemorySize, smem_out);

    k_node<<<296, 256, smem_node>>>(node_input, W_src, b_src, W_dst);
    k_edgeA<<<296, 256, smem_eA>>>(edge_scal, edge_attr, esrc, edst,
                                   rW1, rb1, lng, lnb, rW2, roff, Wa, ba, adot);
    k_gate<<<592, 256, smem_gate>>>(Wv, bv);
    k_edgeB<<<296, 256, smem_eB>>>(edge_attr, esrc, edst, Wv, bv);
    k_out<<<296, 256, smem_out>>>(Wp, bp, out);
}